// round 1
// baseline (speedup 1.0000x reference)
#include <cuda_runtime.h>

// Problem constants
#define B_  4
#define T_  2048
#define D_  1024
#define H_  16
#define HD_ 64
#define M_  (B_ * T_)        // 8192 rows

// Scratch (device globals — no allocation allowed)
__device__ float g_q[B_ * H_ * T_ * HD_];   // [B,H,T,HD]
__device__ float g_k[B_ * H_ * T_ * HD_];
__device__ float g_v[B_ * H_ * T_ * HD_];
__device__ float g_att[B_ * T_ * D_];       // [B,T,D] attention output

// ---------------------------------------------------------------------------
// Kernel 1: QKV GEMM.  C[8192,3072] = x[8192,1024] @ w_qkv[1024,3072] + b_qkv
// 128x128x8 tiling, 256 threads, 8x8 per-thread microtile.
// Epilogue scatters into g_q/g_k/g_v with [B,H,T,HD] layout.
// ---------------------------------------------------------------------------
__global__ __launch_bounds__(256) void qkv_gemm_kernel(
    const float* __restrict__ A,      // x
    const float* __restrict__ W,      // w_qkv
    const float* __restrict__ bias)   // b_qkv
{
    const int K = D_;          // 1024
    const int N = 3 * D_;      // 3072

    __shared__ float As[8][128];   // A^T tile: As[k][m]
    __shared__ float Bs[8][128];   // Bs[k][n]

    const int tid = threadIdx.x;
    const int tx = tid & 15;
    const int ty = tid >> 4;
    const int m0 = blockIdx.y * 128;
    const int n0 = blockIdx.x * 128;

    const int a_m = tid >> 1;            // 0..127
    const int a_k = (tid & 1) << 2;      // 0 or 4
    const int b_k = tid >> 5;            // 0..7
    const int b_n = (tid & 31) << 2;     // 0..124

    const float* Aptr = A + (long)(m0 + a_m) * K + a_k;
    const float* Wptr = W + (long)b_k * N + n0 + b_n;

    float acc[8][8];
    #pragma unroll
    for (int i = 0; i < 8; i++)
        #pragma unroll
        for (int j = 0; j < 8; j++) acc[i][j] = 0.f;

    for (int k0 = 0; k0 < K; k0 += 8) {
        float4 av = *(const float4*)(Aptr + k0);
        float4 bv = *(const float4*)(Wptr + (long)k0 * N);
        As[a_k + 0][a_m] = av.x;
        As[a_k + 1][a_m] = av.y;
        As[a_k + 2][a_m] = av.z;
        As[a_k + 3][a_m] = av.w;
        *(float4*)&Bs[b_k][b_n] = bv;
        __syncthreads();

        #pragma unroll
        for (int kk = 0; kk < 8; kk++) {
            float4 a0 = *(const float4*)&As[kk][ty * 4];
            float4 a1 = *(const float4*)&As[kk][64 + ty * 4];
            float4 b0 = *(const float4*)&Bs[kk][tx * 4];
            float4 b1 = *(const float4*)&Bs[kk][64 + tx * 4];
            float a[8] = {a0.x, a0.y, a0.z, a0.w, a1.x, a1.y, a1.z, a1.w};
            float b[8] = {b0.x, b0.y, b0.z, b0.w, b1.x, b1.y, b1.z, b1.w};
            #pragma unroll
            for (int i = 0; i < 8; i++)
                #pragma unroll
                for (int j = 0; j < 8; j++)
                    acc[i][j] += a[i] * b[j];
        }
        __syncthreads();
    }

    // Epilogue: add bias, scatter to q/k/v in [B,H,T,HD]
    #pragma unroll
    for (int i = 0; i < 8; i++) {
        int mrow = (i < 4) ? (ty * 4 + i) : (64 + ty * 4 + (i - 4));
        int m = m0 + mrow;
        int bidx = m >> 11;           // /2048
        int t = m & (T_ - 1);
        #pragma unroll
        for (int j = 0; j < 8; j++) {
            int ncol = (j < 4) ? (tx * 4 + j) : (64 + tx * 4 + (j - 4));
            int n = n0 + ncol;
            float v = acc[i][j] + bias[n];
            int which = n >> 10;           // 0=q 1=k 2=v
            int rem = n & 1023;
            int h = rem >> 6;
            int hd = rem & 63;
            int idx = ((bidx * H_ + h) * T_ + t) * HD_ + hd;
            float* dst = (which == 0) ? g_q : ((which == 1) ? g_k : g_v);
            dst[idx] = v;
        }
    }
}

// ---------------------------------------------------------------------------
// Kernel 2: causal flash attention, fp32.
// grid (T/64, B*H), 256 threads/block. 64x64 Q/K tiles, online softmax.
// Output to g_att in [B,T,H,HD] (== [B,T,D]) layout for the proj GEMM.
// ---------------------------------------------------------------------------
#define ATTN_SMEM_FLOATS (3*64*64 + 64*65 + 3*64 + 4*64)
__global__ __launch_bounds__(256) void attn_kernel()
{
    extern __shared__ float sm[];
    float* Qs    = sm;                 // [d][m]  4096
    float* Ks    = Qs + 4096;          // [d][n]  4096
    float* Vs    = Ks + 4096;          // [n][d]  4096
    float* Ss    = Vs + 4096;          // [m][65] 4160
    float* m_i   = Ss + 64 * 65;       // 64
    float* l_i   = m_i + 64;           // 64
    float* alpha = l_i + 64;           // 64
    float* red   = alpha + 64;         // [4][64] 256

    const int tid = threadIdx.x;
    const int tx = tid & 15;
    const int ty = tid >> 4;
    const int qt = blockIdx.x;     // query tile 0..31
    const int bh = blockIdx.y;     // 0..63
    const float scale = 0.125f;    // 1/sqrt(64)

    const float* Qg = g_q + ((long)bh * T_ + qt * 64) * HD_;
    const float* Kg = g_k + (long)bh * T_ * HD_;
    const float* Vg = g_v + (long)bh * T_ * HD_;

    // Load Q tile transposed: Qs[d][m]
    {
        int m = tid >> 2;
        int d0 = (tid & 3) << 4;
        #pragma unroll
        for (int c = 0; c < 4; c++) {
            float4 q4 = *(const float4*)(Qg + m * HD_ + d0 + c * 4);
            Qs[(d0 + c * 4 + 0) * 64 + m] = q4.x;
            Qs[(d0 + c * 4 + 1) * 64 + m] = q4.y;
            Qs[(d0 + c * 4 + 2) * 64 + m] = q4.z;
            Qs[(d0 + c * 4 + 3) * 64 + m] = q4.w;
        }
    }
    if (tid < 64) { m_i[tid] = -1e30f; l_i[tid] = 0.f; }

    float acc[4][4] = {};

    for (int kb = 0; kb <= qt; kb++) {
        // Load K tile transposed (Ks[d][n]) and V tile natural (Vs[n][d])
        {
            int n = tid >> 2;
            int d0 = (tid & 3) << 4;
            const float* kp = Kg + (kb * 64 + n) * HD_ + d0;
            const float* vp = Vg + (kb * 64 + n) * HD_ + d0;
            #pragma unroll
            for (int c = 0; c < 4; c++) {
                float4 k4 = *(const float4*)(kp + c * 4);
                Ks[(d0 + c * 4 + 0) * 64 + n] = k4.x;
                Ks[(d0 + c * 4 + 1) * 64 + n] = k4.y;
                Ks[(d0 + c * 4 + 2) * 64 + n] = k4.z;
                Ks[(d0 + c * 4 + 3) * 64 + n] = k4.w;
                *(float4*)(Vs + n * 64 + d0 + c * 4) = *(const float4*)(vp + c * 4);
            }
        }
        __syncthreads();

        // S = Q @ K^T (per-thread 4x4)
        float s[4][4] = {};
        #pragma unroll 8
        for (int d = 0; d < 64; d++) {
            float4 q4 = *(const float4*)(Qs + d * 64 + ty * 4);
            float4 k4 = *(const float4*)(Ks + d * 64 + tx * 4);
            float qa[4] = {q4.x, q4.y, q4.z, q4.w};
            float ka[4] = {k4.x, k4.y, k4.z, k4.w};
            #pragma unroll
            for (int i = 0; i < 4; i++)
                #pragma unroll
                for (int j = 0; j < 4; j++)
                    s[i][j] += qa[i] * ka[j];
        }

        // scale + causal mask + store to smem
        #pragma unroll
        for (int i = 0; i < 4; i++) {
            int qrow = qt * 64 + ty * 4 + i;
            #pragma unroll
            for (int j = 0; j < 4; j++) {
                int kcol = kb * 64 + tx * 4 + j;
                float v = s[i][j] * scale;
                if (kcol > qrow) v = -1e30f;
                Ss[(ty * 4 + i) * 65 + tx * 4 + j] = v;
            }
        }
        __syncthreads();

        // Online softmax, spread across all 256 threads (4 segs x 64 rows)
        const int r = tid & 63;
        const int seg = tid >> 6;
        float* row = Ss + r * 65 + seg * 16;

        float pm = -1e30f;
        #pragma unroll
        for (int c = 0; c < 16; c++) pm = fmaxf(pm, row[c]);
        red[seg * 64 + r] = pm;
        __syncthreads();

        if (tid < 64) {
            float mx = fmaxf(fmaxf(red[tid], red[64 + tid]),
                             fmaxf(red[128 + tid], red[192 + tid]));
            mx = fmaxf(mx, m_i[tid]);
            alpha[tid] = __expf(m_i[tid] - mx);
            m_i[tid] = mx;
        }
        __syncthreads();

        {
            float mx = m_i[r];
            float sum = 0.f;
            #pragma unroll
            for (int c = 0; c < 16; c++) {
                float p = __expf(row[c] - mx);
                row[c] = p;
                sum += p;
            }
            red[seg * 64 + r] = sum;
        }
        __syncthreads();

        if (tid < 64)
            l_i[tid] = l_i[tid] * alpha[tid]
                     + red[tid] + red[64 + tid] + red[128 + tid] + red[192 + tid];

        // rescale accumulators
        #pragma unroll
        for (int i = 0; i < 4; i++) {
            float a = alpha[ty * 4 + i];
            #pragma unroll
            for (int j = 0; j < 4; j++) acc[i][j] *= a;
        }

        // O += P @ V
        #pragma unroll 4
        for (int n = 0; n < 64; n++) {
            float4 v4 = *(const float4*)(Vs + n * 64 + tx * 4);
            float va[4] = {v4.x, v4.y, v4.z, v4.w};
            #pragma unroll
            for (int i = 0; i < 4; i++) {
                float p = Ss[(ty * 4 + i) * 65 + n];
                #pragma unroll
                for (int j = 0; j < 4; j++)
                    acc[i][j] += p * va[j];
            }
        }
        __syncthreads();
    }

    // Epilogue: normalize and write to [B,T,H,HD]
    const int bidx = bh >> 4;
    const int h = bh & 15;
    #pragma unroll
    for (int i = 0; i < 4; i++) {
        int r = ty * 4 + i;
        float inv = 1.0f / l_i[r];
        int t = qt * 64 + r;
        float4 o;
        o.x = acc[i][0] * inv;
        o.y = acc[i][1] * inv;
        o.z = acc[i][2] * inv;
        o.w = acc[i][3] * inv;
        *(float4*)(g_att + ((long)(bidx * T_ + t)) * D_ + h * HD_ + tx * 4) = o;
    }
}

// ---------------------------------------------------------------------------
// Kernel 3: proj GEMM.  out[8192,1024] = g_att @ w_proj[1024,1024] + b_proj
// Same 128x128x8 scheme.
// ---------------------------------------------------------------------------
__global__ __launch_bounds__(256) void proj_gemm_kernel(
    const float* __restrict__ W,      // w_proj
    const float* __restrict__ bias,   // b_proj
    float* __restrict__ C)            // d_out
{
    const int K = D_;     // 1024
    const int N = D_;     // 1024

    __shared__ float As[8][128];
    __shared__ float Bs[8][128];

    const int tid = threadIdx.x;
    const int tx = tid & 15;
    const int ty = tid >> 4;
    const int m0 = blockIdx.y * 128;
    const int n0 = blockIdx.x * 128;

    const int a_m = tid >> 1;
    const int a_k = (tid & 1) << 2;
    const int b_k = tid >> 5;
    const int b_n = (tid & 31) << 2;

    const float* Aptr = g_att + (long)(m0 + a_m) * K + a_k;
    const float* Wptr = W + (long)b_k * N + n0 + b_n;

    float acc[8][8];
    #pragma unroll
    for (int i = 0; i < 8; i++)
        #pragma unroll
        for (int j = 0; j < 8; j++) acc[i][j] = 0.f;

    for (int k0 = 0; k0 < K; k0 += 8) {
        float4 av = *(const float4*)(Aptr + k0);
        float4 bv = *(const float4*)(Wptr + (long)k0 * N);
        As[a_k + 0][a_m] = av.x;
        As[a_k + 1][a_m] = av.y;
        As[a_k + 2][a_m] = av.z;
        As[a_k + 3][a_m] = av.w;
        *(float4*)&Bs[b_k][b_n] = bv;
        __syncthreads();

        #pragma unroll
        for (int kk = 0; kk < 8; kk++) {
            float4 a0 = *(const float4*)&As[kk][ty * 4];
            float4 a1 = *(const float4*)&As[kk][64 + ty * 4];
            float4 b0 = *(const float4*)&Bs[kk][tx * 4];
            float4 b1 = *(const float4*)&Bs[kk][64 + tx * 4];
            float a[8] = {a0.x, a0.y, a0.z, a0.w, a1.x, a1.y, a1.z, a1.w};
            float b[8] = {b0.x, b0.y, b0.z, b0.w, b1.x, b1.y, b1.z, b1.w};
            #pragma unroll
            for (int i = 0; i < 8; i++)
                #pragma unroll
                for (int j = 0; j < 8; j++)
                    acc[i][j] += a[i] * b[j];
        }
        __syncthreads();
    }

    #pragma unroll
    for (int i = 0; i < 8; i++) {
        int m = m0 + ((i < 4) ? (ty * 4 + i) : (64 + ty * 4 + (i - 4)));
        #pragma unroll
        for (int j = 0; j < 8; j++) {
            int n = n0 + ((j < 4) ? (tx * 4 + j) : (64 + tx * 4 + (j - 4)));
            C[(long)m * N + n] = acc[i][j] + bias[n];
        }
    }
}

// ---------------------------------------------------------------------------
extern "C" void kernel_launch(void* const* d_in, const int* in_sizes, int n_in,
                              void* d_out, int out_size)
{
    const float* x      = (const float*)d_in[0];
    const float* w_qkv  = (const float*)d_in[1];
    const float* b_qkv  = (const float*)d_in[2];
    const float* w_proj = (const float*)d_in[3];
    const float* b_proj = (const float*)d_in[4];
    float* out = (float*)d_out;

    // 1) QKV GEMM + scatter
    dim3 g1(3 * D_ / 128, M_ / 128);   // (24, 64)
    qkv_gemm_kernel<<<g1, 256>>>(x, w_qkv, b_qkv);

    // 2) flash attention
    const int attn_smem = ATTN_SMEM_FLOATS * (int)sizeof(float);
    cudaFuncSetAttribute((const void*)attn_kernel,
                         cudaFuncAttributeMaxDynamicSharedMemorySize, attn_smem);
    attn_kernel<<<dim3(T_ / 64, B_ * H_), 256, attn_smem>>>();

    // 3) proj GEMM
    dim3 g3(D_ / 128, M_ / 128);       // (8, 64)
    proj_gemm_kernel<<<g3, 256>>>(w_proj, b_proj, out);
}

// round 3
// speedup vs baseline: 1.6705x; 1.6705x over previous
#include <cuda_runtime.h>
#include <cuda_bf16.h>
#include <cstdint>

// Problem constants
#define B_  4
#define T_  2048
#define D_  1024
#define H_  16
#define HD_ 64
#define M_  (B_ * T_)        // 8192

// Scratch (device globals — no allocation allowed)
__device__ float g_q[B_ * H_ * T_ * HD_];   // [B,H,T,HD]
__device__ float g_k[B_ * H_ * T_ * HD_];
__device__ float g_v[B_ * H_ * T_ * HD_];
// bf16 hi/lo operands
__device__ __nv_bfloat16 g_xhi[M_ * D_];        // x split       [M,K]
__device__ __nv_bfloat16 g_xlo[M_ * D_];
__device__ __nv_bfloat16 g_wqhi[D_ * 3 * D_];   // w_qkv split   [K,N]
__device__ __nv_bfloat16 g_wqlo[D_ * 3 * D_];
__device__ __nv_bfloat16 g_wphi[D_ * D_];       // w_proj split  [K,N]
__device__ __nv_bfloat16 g_wplo[D_ * D_];
__device__ __nv_bfloat16 g_ahi[M_ * D_];        // attention out [M,K]
__device__ __nv_bfloat16 g_alo[M_ * D_];

// ---------------------------------------------------------------------------
__device__ __forceinline__ uint32_t smem_u32(const void* p) {
    uint32_t a;
    asm("{ .reg .u64 t; cvta.to.shared.u64 t, %1; cvt.u32.u64 %0, t; }"
        : "=r"(a) : "l"(p));
    return a;
}

#define CP_ASYNC16(saddr, gaddr) \
    asm volatile("cp.async.cg.shared.global [%0], [%1], 16;" \
                 :: "r"(saddr), "l"(gaddr))
#define CP_COMMIT()  asm volatile("cp.async.commit_group;")
#define CP_WAIT1()   asm volatile("cp.async.wait_group 1;")
#define CP_WAIT0()   asm volatile("cp.async.wait_group 0;")

#define LDSM_X4(r0, r1, r2, r3, addr) \
    asm volatile("ldmatrix.sync.aligned.m8n8.x4.shared.b16 {%0,%1,%2,%3}, [%4];" \
                 : "=r"(r0), "=r"(r1), "=r"(r2), "=r"(r3) : "r"(addr))
#define LDSM_X4T(r0, r1, r2, r3, addr) \
    asm volatile("ldmatrix.sync.aligned.m8n8.x4.trans.shared.b16 {%0,%1,%2,%3}, [%4];" \
                 : "=r"(r0), "=r"(r1), "=r"(r2), "=r"(r3) : "r"(addr))

#define MMA_BF16(c, a, b0, b1) \
    asm volatile("mma.sync.aligned.m16n8k16.row.col.f32.bf16.bf16.f32 " \
        "{%0,%1,%2,%3}, {%4,%5,%6,%7}, {%8,%9}, {%0,%1,%2,%3};" \
        : "+f"((c)[0]), "+f"((c)[1]), "+f"((c)[2]), "+f"((c)[3]) \
        : "r"((a)[0]), "r"((a)[1]), "r"((a)[2]), "r"((a)[3]), "r"(b0), "r"(b1))

// ---------------------------------------------------------------------------
// Prep: elementwise fp32 -> bf16 hi/lo split (layouts unchanged)
// ---------------------------------------------------------------------------
__global__ void split_kernel(const float* __restrict__ src,
                             __nv_bfloat16* __restrict__ hi,
                             __nv_bfloat16* __restrict__ lo, int n)
{
    int i = (blockIdx.x * 256 + threadIdx.x) * 4;
    if (i >= n) return;
    float4 v = *(const float4*)(src + i);
    __nv_bfloat16 h[4], l[4];
    float a[4] = {v.x, v.y, v.z, v.w};
    #pragma unroll
    for (int j = 0; j < 4; j++) {
        h[j] = __float2bfloat16(a[j]);
        l[j] = __float2bfloat16(a[j] - __bfloat162float(h[j]));
    }
    *(uint2*)(hi + i) = *(uint2*)h;
    *(uint2*)(lo + i) = *(uint2*)l;
}

// ---------------------------------------------------------------------------
// bf16x3 GEMM via mma.sync.  C[M,N] = A[M,1024] @ B[1024,N] + bias
// A,B pre-split into bf16 hi/lo.  acc += Ah*Bh + Ah*Bl + Al*Bh (fp32 accum).
// 128x128 CTA tile, BK=32, 8 warps (64x32 warp tiles), cp.async double buffer.
// EPI=0: plain store.  EPI=1: QKV scatter into g_q/g_k/g_v (fp32).
// smem per stage 32KB: [Ahi 8K][Alo 8K][Bhi 8K][Blo 8K], XOR-swizzled.
// ---------------------------------------------------------------------------
#define GEMM_SMEM 65536

template <int EPI>
__global__ __launch_bounds__(256) void gemm_bf16x3(
    const __nv_bfloat16* __restrict__ Ahi, const __nv_bfloat16* __restrict__ Alo,
    const __nv_bfloat16* __restrict__ Bhi, const __nv_bfloat16* __restrict__ Blo,
    const float* __restrict__ bias, float* __restrict__ C, int N)
{
    extern __shared__ char sm[];
    const uint32_t sb = smem_u32(sm);
    const int tid = threadIdx.x;
    const int warp = tid >> 5, lane = tid & 31;
    const int m0 = blockIdx.y * 128, n0 = blockIdx.x * 128;
    const int K = 1024;

    // producer unit coords (16B units)
    const int a_r0 = (tid * 2) >> 2,     a_c0 = (tid * 2) & 3;
    const int a_r1 = (tid * 2 + 1) >> 2, a_c1 = (tid * 2 + 1) & 3;
    const int b_r0 = (tid * 2) >> 4,     b_c0 = (tid * 2) & 15;
    const int b_r1 = (tid * 2 + 1) >> 4, b_c1 = (tid * 2 + 1) & 15;

    auto load_stage = [&](int c, int buf) {
        const uint32_t st = sb + buf * 32768;
        #pragma unroll
        for (int part = 0; part < 2; part++) {
            const __nv_bfloat16* Ap = part ? Alo : Ahi;
            const __nv_bfloat16* Bp = part ? Blo : Bhi;
            const uint32_t ao = st + part * 8192;
            const uint32_t bo = st + 16384 + part * 8192;
            CP_ASYNC16(ao + a_r0 * 64 + ((a_c0 ^ (a_r0 & 3)) << 4),
                       Ap + (long)(m0 + a_r0) * K + c * 32 + a_c0 * 8);
            CP_ASYNC16(ao + a_r1 * 64 + ((a_c1 ^ (a_r1 & 3)) << 4),
                       Ap + (long)(m0 + a_r1) * K + c * 32 + a_c1 * 8);
            CP_ASYNC16(bo + b_r0 * 256 + ((b_c0 ^ (b_r0 & 7)) << 4),
                       Bp + (long)(c * 32 + b_r0) * N + n0 + b_c0 * 8);
            CP_ASYNC16(bo + b_r1 * 256 + ((b_c1 ^ (b_r1 & 7)) << 4),
                       Bp + (long)(c * 32 + b_r1) * N + n0 + b_c1 * 8);
        }
        CP_COMMIT();
    };

    const int wm = (warp & 1) * 64;
    const int wn = (warp >> 1) * 32;

    float acc[4][4][4] = {};

    // consumer lane-derived coords
    const int a_lr = lane & 15;       // A row within m16
    const int a_lk = lane >> 4;       // A k-unit (0/1)
    const int b_lk = lane & 15;       // B k row within k16
    const int b_ln = lane >> 4;       // B n-unit (0/1)
    const int nu0 = wn >> 3;          // first n-unit of warp

    load_stage(0, 0);

    for (int c = 0; c < 32; c++) {
        if (c + 1 < 32) {
            load_stage(c + 1, (c + 1) & 1);
            CP_WAIT1();
        } else {
            CP_WAIT0();
        }
        __syncthreads();

        const uint32_t st = sb + (c & 1) * 32768;
        #pragma unroll
        for (int ks = 0; ks < 2; ks++) {
            uint32_t ah[4][4], al[4][4];
            #pragma unroll
            for (int mi = 0; mi < 4; mi++) {
                const int row = wm + mi * 16 + a_lr;
                const int ku = ks * 2 + a_lk;
                const uint32_t off = row * 64 + ((ku ^ (row & 3)) << 4);
                LDSM_X4(ah[mi][0], ah[mi][1], ah[mi][2], ah[mi][3], st + off);
                LDSM_X4(al[mi][0], al[mi][1], al[mi][2], al[mi][3], st + 8192 + off);
            }
            #pragma unroll
            for (int bi = 0; bi < 2; bi++) {
                const int krow = ks * 16 + b_lk;
                const int nu = nu0 + bi * 2 + b_ln;
                const uint32_t boff = krow * 256 + ((nu ^ (krow & 7)) << 4);
                uint32_t bh[4], bl[4];
                LDSM_X4T(bh[0], bh[1], bh[2], bh[3], st + 16384 + boff);
                LDSM_X4T(bl[0], bl[1], bl[2], bl[3], st + 24576 + boff);
                #pragma unroll
                for (int mi = 0; mi < 4; mi++) {
                    MMA_BF16(acc[mi][bi * 2],     ah[mi], bh[0], bh[1]);
                    MMA_BF16(acc[mi][bi * 2],     ah[mi], bl[0], bl[1]);
                    MMA_BF16(acc[mi][bi * 2],     al[mi], bh[0], bh[1]);
                    MMA_BF16(acc[mi][bi * 2 + 1], ah[mi], bh[2], bh[3]);
                    MMA_BF16(acc[mi][bi * 2 + 1], ah[mi], bl[2], bl[3]);
                    MMA_BF16(acc[mi][bi * 2 + 1], al[mi], bh[2], bh[3]);
                }
            }
        }
        __syncthreads();
    }

    // Epilogue
    const int tg = lane >> 2, ti = lane & 3;
    #pragma unroll
    for (int mi = 0; mi < 4; mi++) {
        #pragma unroll
        for (int nj = 0; nj < 4; nj++) {
            const int n = n0 + wn + nj * 8 + ti * 2;
            #pragma unroll
            for (int half = 0; half < 2; half++) {
                const int m = m0 + wm + mi * 16 + tg + half * 8;
                float2 o;
                o.x = acc[mi][nj][half * 2 + 0] + __ldg(&bias[n]);
                o.y = acc[mi][nj][half * 2 + 1] + __ldg(&bias[n + 1]);
                if (EPI == 0) {
                    *(float2*)(C + (long)m * N + n) = o;
                } else {
                    const int bidx = m >> 11, t = m & (T_ - 1);
                    const int which = n >> 10;
                    const int rem = n & 1023;
                    const int h = rem >> 6, hd = rem & 63;
                    float* dst = (which == 0) ? g_q : ((which == 1) ? g_k : g_v);
                    *(float2*)(dst + (((long)bidx * H_ + h) * T_ + t) * HD_ + hd) = o;
                }
            }
        }
    }
}

// ---------------------------------------------------------------------------
// Kernel 2: causal flash attention, fp32 (epilogue now emits bf16 hi/lo).
// ---------------------------------------------------------------------------
#define ATTN_SMEM_FLOATS (3*64*64 + 64*65 + 3*64 + 4*64)
__global__ __launch_bounds__(256) void attn_kernel()
{
    extern __shared__ float smf[];
    float* Qs    = smf;
    float* Ks    = Qs + 4096;
    float* Vs    = Ks + 4096;
    float* Ss    = Vs + 4096;
    float* m_i   = Ss + 64 * 65;
    float* l_i   = m_i + 64;
    float* alpha = l_i + 64;
    float* red   = alpha + 64;

    const int tid = threadIdx.x;
    const int tx = tid & 15;
    const int ty = tid >> 4;
    const int qt = blockIdx.x;
    const int bh = blockIdx.y;
    const float scale = 0.125f;

    const float* Qg = g_q + ((long)bh * T_ + qt * 64) * HD_;
    const float* Kg = g_k + (long)bh * T_ * HD_;
    const float* Vg = g_v + (long)bh * T_ * HD_;

    {
        int m = tid >> 2;
        int d0 = (tid & 3) << 4;
        #pragma unroll
        for (int c = 0; c < 4; c++) {
            float4 q4 = *(const float4*)(Qg + m * HD_ + d0 + c * 4);
            Qs[(d0 + c * 4 + 0) * 64 + m] = q4.x;
            Qs[(d0 + c * 4 + 1) * 64 + m] = q4.y;
            Qs[(d0 + c * 4 + 2) * 64 + m] = q4.z;
            Qs[(d0 + c * 4 + 3) * 64 + m] = q4.w;
        }
    }
    if (tid < 64) { m_i[tid] = -1e30f; l_i[tid] = 0.f; }

    float acc[4][4] = {};

    for (int kb = 0; kb <= qt; kb++) {
        {
            int n = tid >> 2;
            int d0 = (tid & 3) << 4;
            const float* kp = Kg + (kb * 64 + n) * HD_ + d0;
            const float* vp = Vg + (kb * 64 + n) * HD_ + d0;
            #pragma unroll
            for (int c = 0; c < 4; c++) {
                float4 k4 = *(const float4*)(kp + c * 4);
                Ks[(d0 + c * 4 + 0) * 64 + n] = k4.x;
                Ks[(d0 + c * 4 + 1) * 64 + n] = k4.y;
                Ks[(d0 + c * 4 + 2) * 64 + n] = k4.z;
                Ks[(d0 + c * 4 + 3) * 64 + n] = k4.w;
                *(float4*)(Vs + n * 64 + d0 + c * 4) = *(const float4*)(vp + c * 4);
            }
        }
        __syncthreads();

        float s[4][4] = {};
        #pragma unroll 8
        for (int d = 0; d < 64; d++) {
            float4 q4 = *(const float4*)(Qs + d * 64 + ty * 4);
            float4 k4 = *(const float4*)(Ks + d * 64 + tx * 4);
            float qa[4] = {q4.x, q4.y, q4.z, q4.w};
            float ka[4] = {k4.x, k4.y, k4.z, k4.w};
            #pragma unroll
            for (int i = 0; i < 4; i++)
                #pragma unroll
                for (int j = 0; j < 4; j++)
                    s[i][j] += qa[i] * ka[j];
        }

        #pragma unroll
        for (int i = 0; i < 4; i++) {
            int qrow = qt * 64 + ty * 4 + i;
            #pragma unroll
            for (int j = 0; j < 4; j++) {
                int kcol = kb * 64 + tx * 4 + j;
                float v = s[i][j] * scale;
                if (kcol > qrow) v = -1e30f;
                Ss[(ty * 4 + i) * 65 + tx * 4 + j] = v;
            }
        }
        __syncthreads();

        const int r = tid & 63;
        const int seg = tid >> 6;
        float* rowp = Ss + r * 65 + seg * 16;

        float pm = -1e30f;
        #pragma unroll
        for (int c = 0; c < 16; c++) pm = fmaxf(pm, rowp[c]);
        red[seg * 64 + r] = pm;
        __syncthreads();

        if (tid < 64) {
            float mx = fmaxf(fmaxf(red[tid], red[64 + tid]),
                             fmaxf(red[128 + tid], red[192 + tid]));
            mx = fmaxf(mx, m_i[tid]);
            alpha[tid] = __expf(m_i[tid] - mx);
            m_i[tid] = mx;
        }
        __syncthreads();

        {
            float mx = m_i[r];
            float sum = 0.f;
            #pragma unroll
            for (int c = 0; c < 16; c++) {
                float p = __expf(rowp[c] - mx);
                rowp[c] = p;
                sum += p;
            }
            red[seg * 64 + r] = sum;
        }
        __syncthreads();

        if (tid < 64)
            l_i[tid] = l_i[tid] * alpha[tid]
                     + red[tid] + red[64 + tid] + red[128 + tid] + red[192 + tid];

        #pragma unroll
        for (int i = 0; i < 4; i++) {
            float a = alpha[ty * 4 + i];
            #pragma unroll
            for (int j = 0; j < 4; j++) acc[i][j] *= a;
        }

        #pragma unroll 4
        for (int n = 0; n < 64; n++) {
            float4 v4 = *(const float4*)(Vs + n * 64 + tx * 4);
            float va[4] = {v4.x, v4.y, v4.z, v4.w};
            #pragma unroll
            for (int i = 0; i < 4; i++) {
                float p = Ss[(ty * 4 + i) * 65 + n];
                #pragma unroll
                for (int j = 0; j < 4; j++)
                    acc[i][j] += p * va[j];
            }
        }
        __syncthreads();
    }

    // Epilogue: normalize, split to bf16 hi/lo, write [B,T,H,HD]
    const int bidx = bh >> 4;
    const int h = bh & 15;
    #pragma unroll
    for (int i = 0; i < 4; i++) {
        int r = ty * 4 + i;
        float inv = 1.0f / l_i[r];
        int t = qt * 64 + r;
        float o[4];
        o[0] = acc[i][0] * inv;
        o[1] = acc[i][1] * inv;
        o[2] = acc[i][2] * inv;
        o[3] = acc[i][3] * inv;
        __nv_bfloat16 hi4[4], lo4[4];
        #pragma unroll
        for (int j = 0; j < 4; j++) {
            hi4[j] = __float2bfloat16(o[j]);
            lo4[j] = __float2bfloat16(o[j] - __bfloat162float(hi4[j]));
        }
        long off = ((long)(bidx * T_ + t)) * D_ + h * HD_ + tx * 4;
        *(uint2*)(g_ahi + off) = *(uint2*)hi4;
        *(uint2*)(g_alo + off) = *(uint2*)lo4;
    }
}

// ---------------------------------------------------------------------------
extern "C" void kernel_launch(void* const* d_in, const int* in_sizes, int n_in,
                              void* d_out, int out_size)
{
    const float* x      = (const float*)d_in[0];
    const float* w_qkv  = (const float*)d_in[1];
    const float* b_qkv  = (const float*)d_in[2];
    const float* w_proj = (const float*)d_in[3];
    const float* b_proj = (const float*)d_in[4];
    float* out = (float*)d_out;

    __nv_bfloat16 *xhi, *xlo, *wqhi, *wqlo, *wphi, *wplo, *ahi, *alo;
    cudaGetSymbolAddress((void**)&xhi,  g_xhi);
    cudaGetSymbolAddress((void**)&xlo,  g_xlo);
    cudaGetSymbolAddress((void**)&wqhi, g_wqhi);
    cudaGetSymbolAddress((void**)&wqlo, g_wqlo);
    cudaGetSymbolAddress((void**)&wphi, g_wphi);
    cudaGetSymbolAddress((void**)&wplo, g_wplo);
    cudaGetSymbolAddress((void**)&ahi,  g_ahi);
    cudaGetSymbolAddress((void**)&alo,  g_alo);

    // 0) bf16 hi/lo splits
    split_kernel<<<(M_ * D_) / 1024, 256>>>(x, xhi, xlo, M_ * D_);
    split_kernel<<<(D_ * 3 * D_) / 1024, 256>>>(w_qkv, wqhi, wqlo, D_ * 3 * D_);
    split_kernel<<<(D_ * D_) / 1024, 256>>>(w_proj, wphi, wplo, D_ * D_);

    // 1) QKV GEMM (bf16x3 mma.sync) + scatter to fp32 q/k/v
    cudaFuncSetAttribute((const void*)gemm_bf16x3<1>,
                         cudaFuncAttributeMaxDynamicSharedMemorySize, GEMM_SMEM);
    gemm_bf16x3<1><<<dim3(3 * D_ / 128, M_ / 128), 256, GEMM_SMEM>>>(
        xhi, xlo, wqhi, wqlo, b_qkv, nullptr, 3 * D_);

    // 2) flash attention (fp32 SIMT), epilogue emits bf16 hi/lo
    const int attn_smem = ATTN_SMEM_FLOATS * (int)sizeof(float);
    cudaFuncSetAttribute((const void*)attn_kernel,
                         cudaFuncAttributeMaxDynamicSharedMemorySize, attn_smem);
    attn_kernel<<<dim3(T_ / 64, B_ * H_), 256, attn_smem>>>();

    // 3) proj GEMM (bf16x3 mma.sync)
    cudaFuncSetAttribute((const void*)gemm_bf16x3<0>,
                         cudaFuncAttributeMaxDynamicSharedMemorySize, GEMM_SMEM);
    gemm_bf16x3<0><<<dim3(D_ / 128, M_ / 128), 256, GEMM_SMEM>>>(
        ahi, alo, wphi, wplo, b_proj, out, D_);
}

// round 4
// speedup vs baseline: 2.7179x; 1.6270x over previous
#include <cuda_runtime.h>
#include <cuda_bf16.h>
#include <cstdint>

// Problem constants
#define B_  4
#define T_  2048
#define D_  1024
#define H_  16
#define HD_ 64
#define M_  (B_ * T_)        // 8192

// Scratch (device globals — no allocation allowed)
__device__ __nv_bfloat16 g_qh[B_ * H_ * T_ * HD_];   // [B,H,T,HD] hi/lo
__device__ __nv_bfloat16 g_ql[B_ * H_ * T_ * HD_];
__device__ __nv_bfloat16 g_kh[B_ * H_ * T_ * HD_];
__device__ __nv_bfloat16 g_kl[B_ * H_ * T_ * HD_];
__device__ __nv_bfloat16 g_vh[B_ * H_ * T_ * HD_];
__device__ __nv_bfloat16 g_vl[B_ * H_ * T_ * HD_];
__device__ __nv_bfloat16 g_xhi[M_ * D_];        // x split       [M,K]
__device__ __nv_bfloat16 g_xlo[M_ * D_];
__device__ __nv_bfloat16 g_wqhi[D_ * 3 * D_];   // w_qkv split   [K,N]
__device__ __nv_bfloat16 g_wqlo[D_ * 3 * D_];
__device__ __nv_bfloat16 g_wphi[D_ * D_];       // w_proj split  [K,N]
__device__ __nv_bfloat16 g_wplo[D_ * D_];
__device__ __nv_bfloat16 g_ahi[M_ * D_];        // attention out [M,K]
__device__ __nv_bfloat16 g_alo[M_ * D_];

// ---------------------------------------------------------------------------
__device__ __forceinline__ uint32_t smem_u32(const void* p) {
    uint32_t a;
    asm("{ .reg .u64 t; cvta.to.shared.u64 t, %1; cvt.u32.u64 %0, t; }"
        : "=r"(a) : "l"(p));
    return a;
}

#define CP_ASYNC16(saddr, gaddr) \
    asm volatile("cp.async.cg.shared.global [%0], [%1], 16;" \
                 :: "r"(saddr), "l"(gaddr))
#define CP_COMMIT()  asm volatile("cp.async.commit_group;")
#define CP_WAIT1()   asm volatile("cp.async.wait_group 1;")
#define CP_WAIT0()   asm volatile("cp.async.wait_group 0;")

#define LDSM_X4(r0, r1, r2, r3, addr) \
    asm volatile("ldmatrix.sync.aligned.m8n8.x4.shared.b16 {%0,%1,%2,%3}, [%4];" \
                 : "=r"(r0), "=r"(r1), "=r"(r2), "=r"(r3) : "r"(addr))
#define LDSM_X4T(r0, r1, r2, r3, addr) \
    asm volatile("ldmatrix.sync.aligned.m8n8.x4.trans.shared.b16 {%0,%1,%2,%3}, [%4];" \
                 : "=r"(r0), "=r"(r1), "=r"(r2), "=r"(r3) : "r"(addr))

#define MMA_BF16(c, a, b0, b1) \
    asm volatile("mma.sync.aligned.m16n8k16.row.col.f32.bf16.bf16.f32 " \
        "{%0,%1,%2,%3}, {%4,%5,%6,%7}, {%8,%9}, {%0,%1,%2,%3};" \
        : "+f"((c)[0]), "+f"((c)[1]), "+f"((c)[2]), "+f"((c)[3]) \
        : "r"((a)[0]), "r"((a)[1]), "r"((a)[2]), "r"((a)[3]), "r"(b0), "r"(b1))

// pack two fp32 -> bf16x2 (lo in low half)
__device__ __forceinline__ uint32_t pack2bf(float lo, float hi) {
    uint32_t r;
    asm("cvt.rn.bf16x2.f32 %0, %1, %2;" : "=r"(r) : "f"(hi), "f"(lo));
    return r;
}
// residual pack: (lo,hi) - bf16(lo,hi)
__device__ __forceinline__ uint32_t resid2bf(uint32_t h, float lo, float hi) {
    float lf = __uint_as_float(h << 16);
    float hf = __uint_as_float(h & 0xffff0000u);
    return pack2bf(lo - lf, hi - hf);
}
__device__ __forceinline__ float ex2(float x) {
    float r;
    asm("ex2.approx.f32 %0, %1;" : "=f"(r) : "f"(x));
    return r;
}

// ---------------------------------------------------------------------------
// Prep: elementwise fp32 -> bf16 hi/lo split
// ---------------------------------------------------------------------------
__global__ void split_kernel(const float* __restrict__ src,
                             __nv_bfloat16* __restrict__ hi,
                             __nv_bfloat16* __restrict__ lo, int n)
{
    int i = (blockIdx.x * 256 + threadIdx.x) * 4;
    if (i >= n) return;
    float4 v = *(const float4*)(src + i);
    uint32_t h0 = pack2bf(v.x, v.y), h1 = pack2bf(v.z, v.w);
    uint32_t l0 = resid2bf(h0, v.x, v.y), l1 = resid2bf(h1, v.z, v.w);
    *(uint2*)(hi + i) = make_uint2(h0, h1);
    *(uint2*)(lo + i) = make_uint2(l0, l1);
}

// ---------------------------------------------------------------------------
// bf16x3 GEMM via mma.sync (as R3).  EPI=0: plain store.  EPI=1: QKV scatter
// into bf16 hi/lo q/k/v arrays [B,H,T,HD].
// ---------------------------------------------------------------------------
#define GEMM_SMEM 65536

template <int EPI>
__global__ __launch_bounds__(256) void gemm_bf16x3(
    const __nv_bfloat16* __restrict__ Ahi, const __nv_bfloat16* __restrict__ Alo,
    const __nv_bfloat16* __restrict__ Bhi, const __nv_bfloat16* __restrict__ Blo,
    const float* __restrict__ bias, float* __restrict__ C, int N)
{
    extern __shared__ char sm[];
    const uint32_t sb = smem_u32(sm);
    const int tid = threadIdx.x;
    const int warp = tid >> 5, lane = tid & 31;
    const int m0 = blockIdx.y * 128, n0 = blockIdx.x * 128;
    const int K = 1024;

    const int a_r0 = (tid * 2) >> 2,     a_c0 = (tid * 2) & 3;
    const int a_r1 = (tid * 2 + 1) >> 2, a_c1 = (tid * 2 + 1) & 3;
    const int b_r0 = (tid * 2) >> 4,     b_c0 = (tid * 2) & 15;
    const int b_r1 = (tid * 2 + 1) >> 4, b_c1 = (tid * 2 + 1) & 15;

    auto load_stage = [&](int c, int buf) {
        const uint32_t st = sb + buf * 32768;
        #pragma unroll
        for (int part = 0; part < 2; part++) {
            const __nv_bfloat16* Ap = part ? Alo : Ahi;
            const __nv_bfloat16* Bp = part ? Blo : Bhi;
            const uint32_t ao = st + part * 8192;
            const uint32_t bo = st + 16384 + part * 8192;
            CP_ASYNC16(ao + a_r0 * 64 + ((a_c0 ^ (a_r0 & 3)) << 4),
                       Ap + (long)(m0 + a_r0) * K + c * 32 + a_c0 * 8);
            CP_ASYNC16(ao + a_r1 * 64 + ((a_c1 ^ (a_r1 & 3)) << 4),
                       Ap + (long)(m0 + a_r1) * K + c * 32 + a_c1 * 8);
            CP_ASYNC16(bo + b_r0 * 256 + ((b_c0 ^ (b_r0 & 7)) << 4),
                       Bp + (long)(c * 32 + b_r0) * N + n0 + b_c0 * 8);
            CP_ASYNC16(bo + b_r1 * 256 + ((b_c1 ^ (b_r1 & 7)) << 4),
                       Bp + (long)(c * 32 + b_r1) * N + n0 + b_c1 * 8);
        }
        CP_COMMIT();
    };

    const int wm = (warp & 1) * 64;
    const int wn = (warp >> 1) * 32;

    float acc[4][4][4] = {};

    const int a_lr = lane & 15;
    const int a_lk = lane >> 4;
    const int b_lk = lane & 15;
    const int b_ln = lane >> 4;
    const int nu0 = wn >> 3;

    load_stage(0, 0);

    for (int c = 0; c < 32; c++) {
        if (c + 1 < 32) {
            load_stage(c + 1, (c + 1) & 1);
            CP_WAIT1();
        } else {
            CP_WAIT0();
        }
        __syncthreads();

        const uint32_t st = sb + (c & 1) * 32768;
        #pragma unroll
        for (int ks = 0; ks < 2; ks++) {
            uint32_t ah[4][4], al[4][4];
            #pragma unroll
            for (int mi = 0; mi < 4; mi++) {
                const int row = wm + mi * 16 + a_lr;
                const int ku = ks * 2 + a_lk;
                const uint32_t off = row * 64 + ((ku ^ (row & 3)) << 4);
                LDSM_X4(ah[mi][0], ah[mi][1], ah[mi][2], ah[mi][3], st + off);
                LDSM_X4(al[mi][0], al[mi][1], al[mi][2], al[mi][3], st + 8192 + off);
            }
            #pragma unroll
            for (int bi = 0; bi < 2; bi++) {
                const int krow = ks * 16 + b_lk;
                const int nu = nu0 + bi * 2 + b_ln;
                const uint32_t boff = krow * 256 + ((nu ^ (krow & 7)) << 4);
                uint32_t bh[4], bl[4];
                LDSM_X4T(bh[0], bh[1], bh[2], bh[3], st + 16384 + boff);
                LDSM_X4T(bl[0], bl[1], bl[2], bl[3], st + 24576 + boff);
                #pragma unroll
                for (int mi = 0; mi < 4; mi++) {
                    MMA_BF16(acc[mi][bi * 2],     ah[mi], bh[0], bh[1]);
                    MMA_BF16(acc[mi][bi * 2],     ah[mi], bl[0], bl[1]);
                    MMA_BF16(acc[mi][bi * 2],     al[mi], bh[0], bh[1]);
                    MMA_BF16(acc[mi][bi * 2 + 1], ah[mi], bh[2], bh[3]);
                    MMA_BF16(acc[mi][bi * 2 + 1], ah[mi], bl[2], bl[3]);
                    MMA_BF16(acc[mi][bi * 2 + 1], al[mi], bh[2], bh[3]);
                }
            }
        }
        __syncthreads();
    }

    // Epilogue
    const int tg = lane >> 2, ti = lane & 3;
    #pragma unroll
    for (int mi = 0; mi < 4; mi++) {
        #pragma unroll
        for (int nj = 0; nj < 4; nj++) {
            const int n = n0 + wn + nj * 8 + ti * 2;
            #pragma unroll
            for (int half = 0; half < 2; half++) {
                const int m = m0 + wm + mi * 16 + tg + half * 8;
                float ox = acc[mi][nj][half * 2 + 0] + __ldg(&bias[n]);
                float oy = acc[mi][nj][half * 2 + 1] + __ldg(&bias[n + 1]);
                if (EPI == 0) {
                    *(float2*)(C + (long)m * N + n) = make_float2(ox, oy);
                } else {
                    const int bidx = m >> 11, t = m & (T_ - 1);
                    const int which = n >> 10;
                    const int rem = n & 1023;
                    const int h = rem >> 6, hd = rem & 63;
                    __nv_bfloat16* dh = (which == 0) ? g_qh : ((which == 1) ? g_kh : g_vh);
                    __nv_bfloat16* dl = (which == 0) ? g_ql : ((which == 1) ? g_kl : g_vl);
                    long off = (((long)bidx * H_ + h) * T_ + t) * HD_ + hd;
                    uint32_t hp = pack2bf(ox, oy);
                    *(uint32_t*)(dh + off) = hp;
                    *(uint32_t*)(dl + off) = resid2bf(hp, ox, oy);
                }
            }
        }
    }
}

// ---------------------------------------------------------------------------
// Tensor-core causal flash attention (bf16x3), FA2 register softmax.
// CTA: 128 q-rows, 8 warps x m16.  kv tiles of 64, cp.async double buffer.
// smem: Qh/Ql 32KB + 2 stages x (Kh,Kl,Vh,Vl 8KB each) = 96KB.
// ---------------------------------------------------------------------------
#define ATTN_SMEM (32768 + 2 * 32768)
#define SCL2 0.1803368801111204f   // 0.125 * log2(e)

__global__ __launch_bounds__(256, 1) void attn_tc_kernel()
{
    extern __shared__ char sm[];
    const uint32_t sb = smem_u32(sm);
    const int tid = threadIdx.x;
    const int w = tid >> 5, lane = tid & 31;
    const int tg = lane >> 2, ti = lane & 3;
    const int qt = 15 - blockIdx.x;           // big tiles first
    const int bh = blockIdx.y;
    const int qbase = qt * 128 + w * 16;
    const int r0 = qbase + tg;                // thread rows r0, r0+8

    const long bhoff = (long)bh * T_ * HD_;

    // ---- issue Q loads (rows of 128B, swizzled) + KV tile 0
    {
        const int row = tid >> 1;
        const int u0 = (tid & 1) * 4;
        const long gq = bhoff + (long)(qt * 128 + row) * HD_;
        #pragma unroll
        for (int i = 0; i < 4; i++) {
            const int u = u0 + i;
            const uint32_t so = row * 128 + ((u ^ (row & 7)) << 4);
            CP_ASYNC16(sb + so,         g_qh + gq + u * 8);
            CP_ASYNC16(sb + 16384 + so, g_ql + gq + u * 8);
        }
    }
    const int kvp = tid >> 6;        // 0..3 -> Kh,Kl,Vh,Vl
    const int kvr = tid & 63;        // row within tile
    const __nv_bfloat16* kvsrc =
        (kvp == 0) ? g_kh : (kvp == 1) ? g_kl : (kvp == 2) ? g_vh : g_vl;
    const uint32_t kvdst_off = kvp * 8192 + kvr * 128;

    auto load_kv = [&](int kb, int buf) {
        const uint32_t st = sb + 32768 + buf * 32768;
        const long gs = bhoff + (long)(kb * 64 + kvr) * HD_;
        #pragma unroll
        for (int u = 0; u < 8; u++)
            CP_ASYNC16(st + kvdst_off + ((u ^ (kvr & 7)) << 4), kvsrc + gs + u * 8);
    };
    load_kv(0, 0);
    CP_COMMIT();
    CP_WAIT0();
    __syncthreads();

    // ---- Q fragments (A-frags, m16k16 per hd-step)
    uint32_t qh[4][4], ql[4][4];
    #pragma unroll
    for (int s = 0; s < 4; s++) {
        const int row = w * 16 + (lane & 15);
        const int ku = s * 2 + (lane >> 4);
        const uint32_t ad = sb + row * 128 + ((ku ^ (row & 7)) << 4);
        LDSM_X4(qh[s][0], qh[s][1], qh[s][2], qh[s][3], ad);
        LDSM_X4(ql[s][0], ql[s][1], ql[s][2], ql[s][3], ad + 16384);
    }

    float oacc[8][4] = {};
    float m2a = -1e30f, m2b = -1e30f;
    float la = 0.f, lb = 0.f;

    const int nt = 2 * qt + 2;
    for (int kb = 0; kb < nt; kb++) {
        if (kb > 0) CP_WAIT0();
        __syncthreads();
        if (kb + 1 < nt) { load_kv(kb + 1, (kb + 1) & 1); CP_COMMIT(); }

        if (kb * 64 > qbase + 15) continue;   // warp fully masked

        const uint32_t stK = sb + 32768 + (kb & 1) * 32768;
        const uint32_t stV = stK + 16384;

        // ---- S = Q K^T (bf16x3)
        float sacc[8][4] = {};
        #pragma unroll
        for (int s = 0; s < 4; s++) {
            #pragma unroll
            for (int g = 0; g < 4; g++) {
                const int row = g * 16 + (lane & 15);
                const uint32_t ka = stK + row * 128 +
                    (((s * 2 + (lane >> 4)) ^ (row & 7)) << 4);
                uint32_t h0, h1, h2, h3, l0, l1, l2, l3;
                LDSM_X4(h0, h1, h2, h3, ka);
                LDSM_X4(l0, l1, l2, l3, ka + 8192);
                MMA_BF16(sacc[2 * g],     qh[s], h0, h2);
                MMA_BF16(sacc[2 * g],     ql[s], h0, h2);
                MMA_BF16(sacc[2 * g],     qh[s], l0, l2);
                MMA_BF16(sacc[2 * g + 1], qh[s], h1, h3);
                MMA_BF16(sacc[2 * g + 1], ql[s], h1, h3);
                MMA_BF16(sacc[2 * g + 1], qh[s], l1, l3);
            }
        }

        // ---- scale to log2-domain + causal mask + row max
        const bool needmask = (kb * 64 + 63) > r0;
        float mra = -1e30f, mrb = -1e30f;
        #pragma unroll
        for (int j = 0; j < 8; j++) {
            const int c0 = kb * 64 + 8 * j + 2 * ti, c1 = c0 + 1;
            float z0 = sacc[j][0] * SCL2;
            float z1 = sacc[j][1] * SCL2;
            float z2 = sacc[j][2] * SCL2;
            float z3 = sacc[j][3] * SCL2;
            if (needmask) {
                if (c0 > r0) z0 = -1e30f;
                if (c1 > r0) z1 = -1e30f;
                if (c0 > r0 + 8) z2 = -1e30f;
                if (c1 > r0 + 8) z3 = -1e30f;
            }
            sacc[j][0] = z0; sacc[j][1] = z1; sacc[j][2] = z2; sacc[j][3] = z3;
            mra = fmaxf(mra, fmaxf(z0, z1));
            mrb = fmaxf(mrb, fmaxf(z2, z3));
        }
        mra = fmaxf(mra, __shfl_xor_sync(0xffffffffu, mra, 1));
        mra = fmaxf(mra, __shfl_xor_sync(0xffffffffu, mra, 2));
        mrb = fmaxf(mrb, __shfl_xor_sync(0xffffffffu, mrb, 1));
        mrb = fmaxf(mrb, __shfl_xor_sync(0xffffffffu, mrb, 2));

        const float mna = fmaxf(m2a, mra);
        const float mnb = fmaxf(m2b, mrb);
        const float alpa = ex2(m2a - mna);
        const float alpb = ex2(m2b - mnb);
        m2a = mna; m2b = mnb;

        #pragma unroll
        for (int j = 0; j < 8; j++) {
            oacc[j][0] *= alpa; oacc[j][1] *= alpa;
            oacc[j][2] *= alpb; oacc[j][3] *= alpb;
        }

        // ---- exp + pack P hi/lo (A-frag layout!)
        uint32_t pha[8], phb[8], pla[8], plb[8];
        float sa = 0.f, sbm = 0.f;
        #pragma unroll
        for (int j = 0; j < 8; j++) {
            float p0 = ex2(sacc[j][0] - m2a);
            float p1 = ex2(sacc[j][1] - m2a);
            float p2 = ex2(sacc[j][2] - m2b);
            float p3 = ex2(sacc[j][3] - m2b);
            sa += p0 + p1; sbm += p2 + p3;
            pha[j] = pack2bf(p0, p1); pla[j] = resid2bf(pha[j], p0, p1);
            phb[j] = pack2bf(p2, p3); plb[j] = resid2bf(phb[j], p2, p3);
        }
        sa  += __shfl_xor_sync(0xffffffffu, sa, 1);
        sa  += __shfl_xor_sync(0xffffffffu, sa, 2);
        sbm += __shfl_xor_sync(0xffffffffu, sbm, 1);
        sbm += __shfl_xor_sync(0xffffffffu, sbm, 2);
        la = la * alpa + sa;
        lb = lb * alpb + sbm;

        // ---- O += P V (bf16x3)
        #pragma unroll
        for (int s = 0; s < 4; s++) {
            uint32_t aH[4] = {pha[2 * s], phb[2 * s], pha[2 * s + 1], phb[2 * s + 1]};
            uint32_t aL[4] = {pla[2 * s], plb[2 * s], pla[2 * s + 1], plb[2 * s + 1]};
            #pragma unroll
            for (int b = 0; b < 4; b++) {
                const int krow = s * 16 + (lane & 15);
                const uint32_t va = stV + krow * 128 +
                    (((b * 2 + (lane >> 4)) ^ (krow & 7)) << 4);
                uint32_t h0, h1, h2, h3, l0, l1, l2, l3;
                LDSM_X4T(h0, h1, h2, h3, va);
                MMA_BF16(oacc[2 * b],     aH, h0, h1);
                MMA_BF16(oacc[2 * b],     aL, h0, h1);
                MMA_BF16(oacc[2 * b + 1], aH, h2, h3);
                MMA_BF16(oacc[2 * b + 1], aL, h2, h3);
                LDSM_X4T(l0, l1, l2, l3, va + 8192);
                MMA_BF16(oacc[2 * b],     aH, l0, l1);
                MMA_BF16(oacc[2 * b + 1], aH, l2, l3);
            }
        }
    }

    // ---- epilogue: normalize, bf16 hi/lo split, write [B,T,H*HD]
    const float inva = 1.0f / la, invb = 1.0f / lb;
    const int bidx = bh >> 4, h = bh & 15;
    const long rowa = ((long)(bidx * T_ + qbase + tg)) * D_ + h * HD_;
    const long rowb = rowa + 8L * D_;
    #pragma unroll
    for (int j = 0; j < 8; j++) {
        const int col = 8 * j + 2 * ti;
        float f0 = oacc[j][0] * inva, f1 = oacc[j][1] * inva;
        float f2 = oacc[j][2] * invb, f3 = oacc[j][3] * invb;
        uint32_t hpa = pack2bf(f0, f1);
        uint32_t hpb = pack2bf(f2, f3);
        *(uint32_t*)(g_ahi + rowa + col) = hpa;
        *(uint32_t*)(g_alo + rowa + col) = resid2bf(hpa, f0, f1);
        *(uint32_t*)(g_ahi + rowb + col) = hpb;
        *(uint32_t*)(g_alo + rowb + col) = resid2bf(hpb, f2, f3);
    }
}

// ---------------------------------------------------------------------------
extern "C" void kernel_launch(void* const* d_in, const int* in_sizes, int n_in,
                              void* d_out, int out_size)
{
    const float* x      = (const float*)d_in[0];
    const float* w_qkv  = (const float*)d_in[1];
    const float* b_qkv  = (const float*)d_in[2];
    const float* w_proj = (const float*)d_in[3];
    const float* b_proj = (const float*)d_in[4];
    float* out = (float*)d_out;

    __nv_bfloat16 *xhi, *xlo, *wqhi, *wqlo, *wphi, *wplo, *ahi, *alo;
    cudaGetSymbolAddress((void**)&xhi,  g_xhi);
    cudaGetSymbolAddress((void**)&xlo,  g_xlo);
    cudaGetSymbolAddress((void**)&wqhi, g_wqhi);
    cudaGetSymbolAddress((void**)&wqlo, g_wqlo);
    cudaGetSymbolAddress((void**)&wphi, g_wphi);
    cudaGetSymbolAddress((void**)&wplo, g_wplo);
    cudaGetSymbolAddress((void**)&ahi,  g_ahi);
    cudaGetSymbolAddress((void**)&alo,  g_alo);

    // 0) bf16 hi/lo splits
    split_kernel<<<(M_ * D_) / 1024, 256>>>(x, xhi, xlo, M_ * D_);
    split_kernel<<<(D_ * 3 * D_) / 1024, 256>>>(w_qkv, wqhi, wqlo, D_ * 3 * D_);
    split_kernel<<<(D_ * D_) / 1024, 256>>>(w_proj, wphi, wplo, D_ * D_);

    // 1) QKV GEMM (bf16x3) -> q/k/v bf16 hi/lo
    cudaFuncSetAttribute((const void*)gemm_bf16x3<1>,
                         cudaFuncAttributeMaxDynamicSharedMemorySize, GEMM_SMEM);
    gemm_bf16x3<1><<<dim3(3 * D_ / 128, M_ / 128), 256, GEMM_SMEM>>>(
        xhi, xlo, wqhi, wqlo, b_qkv, nullptr, 3 * D_);

    // 2) tensor-core flash attention
    cudaFuncSetAttribute((const void*)attn_tc_kernel,
                         cudaFuncAttributeMaxDynamicSharedMemorySize, ATTN_SMEM);
    attn_tc_kernel<<<dim3(T_ / 128, B_ * H_), 256, ATTN_SMEM>>>();

    // 3) proj GEMM (bf16x3)
    cudaFuncSetAttribute((const void*)gemm_bf16x3<0>,
                         cudaFuncAttributeMaxDynamicSharedMemorySize, GEMM_SMEM);
    gemm_bf16x3<0><<<dim3(D_ / 128, M_ / 128), 256, GEMM_SMEM>>>(
        ahi, alo, wphi, wplo, b_proj, out, D_);
}

// round 5
// speedup vs baseline: 2.9193x; 1.0741x over previous
#include <cuda_runtime.h>
#include <cuda_bf16.h>
#include <cstdint>

// Problem constants
#define B_  4
#define T_  2048
#define D_  1024
#define H_  16
#define HD_ 64
#define M_  (B_ * T_)        // 8192

// Scratch (device globals — no allocation allowed)
__device__ __nv_bfloat16 g_qh[B_ * H_ * T_ * HD_];   // [B,H,T,HD] hi/lo
__device__ __nv_bfloat16 g_ql[B_ * H_ * T_ * HD_];
__device__ __nv_bfloat16 g_kh[B_ * H_ * T_ * HD_];
__device__ __nv_bfloat16 g_kl[B_ * H_ * T_ * HD_];
__device__ __nv_bfloat16 g_vh[B_ * H_ * T_ * HD_];
__device__ __nv_bfloat16 g_vl[B_ * H_ * T_ * HD_];
__device__ __nv_bfloat16 g_xhi[M_ * D_];        // x split       [M,K]
__device__ __nv_bfloat16 g_xlo[M_ * D_];
__device__ __nv_bfloat16 g_wqhi[D_ * 3 * D_];   // w_qkv split   [K,N]
__device__ __nv_bfloat16 g_wqlo[D_ * 3 * D_];
__device__ __nv_bfloat16 g_wphi[D_ * D_];       // w_proj split  [K,N]
__device__ __nv_bfloat16 g_wplo[D_ * D_];
__device__ __nv_bfloat16 g_ahi[M_ * D_];        // attention out [M,K]
__device__ __nv_bfloat16 g_alo[M_ * D_];

// ---------------------------------------------------------------------------
__device__ __forceinline__ uint32_t smem_u32(const void* p) {
    uint32_t a;
    asm("{ .reg .u64 t; cvta.to.shared.u64 t, %1; cvt.u32.u64 %0, t; }"
        : "=r"(a) : "l"(p));
    return a;
}

#define CP_ASYNC16(saddr, gaddr) \
    asm volatile("cp.async.cg.shared.global [%0], [%1], 16;" \
                 :: "r"(saddr), "l"(gaddr))
#define CP_COMMIT()  asm volatile("cp.async.commit_group;")
#define CP_WAIT1()   asm volatile("cp.async.wait_group 1;")
#define CP_WAIT0()   asm volatile("cp.async.wait_group 0;")

#define LDSM_X4(r0, r1, r2, r3, addr) \
    asm volatile("ldmatrix.sync.aligned.m8n8.x4.shared.b16 {%0,%1,%2,%3}, [%4];" \
                 : "=r"(r0), "=r"(r1), "=r"(r2), "=r"(r3) : "r"(addr))
#define LDSM_X4T(r0, r1, r2, r3, addr) \
    asm volatile("ldmatrix.sync.aligned.m8n8.x4.trans.shared.b16 {%0,%1,%2,%3}, [%4];" \
                 : "=r"(r0), "=r"(r1), "=r"(r2), "=r"(r3) : "r"(addr))

#define MMA_BF16(c, a, b0, b1) \
    asm volatile("mma.sync.aligned.m16n8k16.row.col.f32.bf16.bf16.f32 " \
        "{%0,%1,%2,%3}, {%4,%5,%6,%7}, {%8,%9}, {%0,%1,%2,%3};" \
        : "+f"((c)[0]), "+f"((c)[1]), "+f"((c)[2]), "+f"((c)[3]) \
        : "r"((a)[0]), "r"((a)[1]), "r"((a)[2]), "r"((a)[3]), "r"(b0), "r"(b1))

// pack two fp32 -> bf16x2 (lo in low half)
__device__ __forceinline__ uint32_t pack2bf(float lo, float hi) {
    uint32_t r;
    asm("cvt.rn.bf16x2.f32 %0, %1, %2;" : "=r"(r) : "f"(hi), "f"(lo));
    return r;
}
// residual pack: (lo,hi) - bf16(lo,hi)
__device__ __forceinline__ uint32_t resid2bf(uint32_t h, float lo, float hi) {
    float lf = __uint_as_float(h << 16);
    float hf = __uint_as_float(h & 0xffff0000u);
    return pack2bf(lo - lf, hi - hf);
}
__device__ __forceinline__ float ex2(float x) {
    float r;
    asm("ex2.approx.f32 %0, %1;" : "=f"(r) : "f"(x));
    return r;
}

// ---------------------------------------------------------------------------
// Prep: elementwise fp32 -> bf16 hi/lo split
// ---------------------------------------------------------------------------
__global__ void split_kernel(const float* __restrict__ src,
                             __nv_bfloat16* __restrict__ hi,
                             __nv_bfloat16* __restrict__ lo, int n)
{
    int i = (blockIdx.x * 256 + threadIdx.x) * 4;
    if (i >= n) return;
    float4 v = *(const float4*)(src + i);
    uint32_t h0 = pack2bf(v.x, v.y), h1 = pack2bf(v.z, v.w);
    uint32_t l0 = resid2bf(h0, v.x, v.y), l1 = resid2bf(h1, v.z, v.w);
    *(uint2*)(hi + i) = make_uint2(h0, h1);
    *(uint2*)(lo + i) = make_uint2(l0, l1);
}

// ---------------------------------------------------------------------------
// bf16x3 GEMM via mma.sync.  __launch_bounds__(256,2) caps regs at 128 so two
// CTAs co-reside per SM (the R4 epilogue pushed regs to 146 -> 1 CTA -> tensor
// pipe starved at syncthreads).  EPI=0: plain store.  EPI=1: QKV scatter.
// ---------------------------------------------------------------------------
#define GEMM_SMEM 65536

template <int EPI>
__global__ __launch_bounds__(256, 2) void gemm_bf16x3(
    const __nv_bfloat16* __restrict__ Ahi, const __nv_bfloat16* __restrict__ Alo,
    const __nv_bfloat16* __restrict__ Bhi, const __nv_bfloat16* __restrict__ Blo,
    const float* __restrict__ bias, float* __restrict__ C, int N)
{
    extern __shared__ char sm[];
    const uint32_t sb = smem_u32(sm);
    const int tid = threadIdx.x;
    const int warp = tid >> 5, lane = tid & 31;
    const int m0 = blockIdx.y * 128, n0 = blockIdx.x * 128;
    const int K = 1024;

    const int a_r0 = (tid * 2) >> 2,     a_c0 = (tid * 2) & 3;
    const int a_r1 = (tid * 2 + 1) >> 2, a_c1 = (tid * 2 + 1) & 3;
    const int b_r0 = (tid * 2) >> 4,     b_c0 = (tid * 2) & 15;
    const int b_r1 = (tid * 2 + 1) >> 4, b_c1 = (tid * 2 + 1) & 15;

    auto load_stage = [&](int c, int buf) {
        const uint32_t st = sb + buf * 32768;
        #pragma unroll
        for (int part = 0; part < 2; part++) {
            const __nv_bfloat16* Ap = part ? Alo : Ahi;
            const __nv_bfloat16* Bp = part ? Blo : Bhi;
            const uint32_t ao = st + part * 8192;
            const uint32_t bo = st + 16384 + part * 8192;
            CP_ASYNC16(ao + a_r0 * 64 + ((a_c0 ^ (a_r0 & 3)) << 4),
                       Ap + (long)(m0 + a_r0) * K + c * 32 + a_c0 * 8);
            CP_ASYNC16(ao + a_r1 * 64 + ((a_c1 ^ (a_r1 & 3)) << 4),
                       Ap + (long)(m0 + a_r1) * K + c * 32 + a_c1 * 8);
            CP_ASYNC16(bo + b_r0 * 256 + ((b_c0 ^ (b_r0 & 7)) << 4),
                       Bp + (long)(c * 32 + b_r0) * N + n0 + b_c0 * 8);
            CP_ASYNC16(bo + b_r1 * 256 + ((b_c1 ^ (b_r1 & 7)) << 4),
                       Bp + (long)(c * 32 + b_r1) * N + n0 + b_c1 * 8);
        }
        CP_COMMIT();
    };

    const int wm = (warp & 1) * 64;
    const int wn = (warp >> 1) * 32;

    float acc[4][4][4] = {};

    const int a_lr = lane & 15;
    const int a_lk = lane >> 4;
    const int b_lk = lane & 15;
    const int b_ln = lane >> 4;
    const int nu0 = wn >> 3;

    load_stage(0, 0);

    for (int c = 0; c < 32; c++) {
        if (c + 1 < 32) {
            load_stage(c + 1, (c + 1) & 1);
            CP_WAIT1();
        } else {
            CP_WAIT0();
        }
        __syncthreads();

        const uint32_t st = sb + (c & 1) * 32768;
        #pragma unroll
        for (int ks = 0; ks < 2; ks++) {
            uint32_t ah[4][4], al[4][4];
            #pragma unroll
            for (int mi = 0; mi < 4; mi++) {
                const int row = wm + mi * 16 + a_lr;
                const int ku = ks * 2 + a_lk;
                const uint32_t off = row * 64 + ((ku ^ (row & 3)) << 4);
                LDSM_X4(ah[mi][0], ah[mi][1], ah[mi][2], ah[mi][3], st + off);
                LDSM_X4(al[mi][0], al[mi][1], al[mi][2], al[mi][3], st + 8192 + off);
            }
            #pragma unroll
            for (int bi = 0; bi < 2; bi++) {
                const int krow = ks * 16 + b_lk;
                const int nu = nu0 + bi * 2 + b_ln;
                const uint32_t boff = krow * 256 + ((nu ^ (krow & 7)) << 4);
                uint32_t bh[4], bl[4];
                LDSM_X4T(bh[0], bh[1], bh[2], bh[3], st + 16384 + boff);
                LDSM_X4T(bl[0], bl[1], bl[2], bl[3], st + 24576 + boff);
                #pragma unroll
                for (int mi = 0; mi < 4; mi++) {
                    MMA_BF16(acc[mi][bi * 2],     ah[mi], bh[0], bh[1]);
                    MMA_BF16(acc[mi][bi * 2],     ah[mi], bl[0], bl[1]);
                    MMA_BF16(acc[mi][bi * 2],     al[mi], bh[0], bh[1]);
                    MMA_BF16(acc[mi][bi * 2 + 1], ah[mi], bh[2], bh[3]);
                    MMA_BF16(acc[mi][bi * 2 + 1], ah[mi], bl[2], bl[3]);
                    MMA_BF16(acc[mi][bi * 2 + 1], al[mi], bh[2], bh[3]);
                }
            }
        }
        __syncthreads();
    }

    // Epilogue
    const int tg = lane >> 2, ti = lane & 3;
    #pragma unroll
    for (int mi = 0; mi < 4; mi++) {
        #pragma unroll
        for (int nj = 0; nj < 4; nj++) {
            const int n = n0 + wn + nj * 8 + ti * 2;
            const float bx = __ldg(&bias[n]), by = __ldg(&bias[n + 1]);
            #pragma unroll
            for (int half = 0; half < 2; half++) {
                const int m = m0 + wm + mi * 16 + tg + half * 8;
                float ox = acc[mi][nj][half * 2 + 0] + bx;
                float oy = acc[mi][nj][half * 2 + 1] + by;
                if (EPI == 0) {
                    *(float2*)(C + (long)m * N + n) = make_float2(ox, oy);
                } else {
                    const int bidx = m >> 11, t = m & (T_ - 1);
                    const int which = n >> 10;
                    const int rem = n & 1023;
                    const int h = rem >> 6, hd = rem & 63;
                    __nv_bfloat16* dh = (which == 0) ? g_qh : ((which == 1) ? g_kh : g_vh);
                    __nv_bfloat16* dl = (which == 0) ? g_ql : ((which == 1) ? g_kl : g_vl);
                    long off = (((long)bidx * H_ + h) * T_ + t) * HD_ + hd;
                    uint32_t hp = pack2bf(ox, oy);
                    *(uint32_t*)(dh + off) = hp;
                    *(uint32_t*)(dl + off) = resid2bf(hp, ox, oy);
                }
            }
        }
    }
}

// ---------------------------------------------------------------------------
// Tensor-core causal flash attention (bf16x3), FA2 register softmax.
// CTA: 128 q-rows, 8 warps x m16.  kv tiles of 64, cp.async double buffer.
// smem: Qh/Ql 32KB + 2 stages x (Kh,Kl,Vh,Vl 8KB each) = 96KB.
// ---------------------------------------------------------------------------
#define ATTN_SMEM (32768 + 2 * 32768)
#define SCL2 0.1803368801111204f   // 0.125 * log2(e)

__global__ __launch_bounds__(256, 1) void attn_tc_kernel()
{
    extern __shared__ char sm[];
    const uint32_t sb = smem_u32(sm);
    const int tid = threadIdx.x;
    const int w = tid >> 5, lane = tid & 31;
    const int tg = lane >> 2, ti = lane & 3;
    const int qt = 15 - blockIdx.x;           // big tiles first
    const int bh = blockIdx.y;
    const int qbase = qt * 128 + w * 16;
    const int r0 = qbase + tg;                // thread rows r0, r0+8

    const long bhoff = (long)bh * T_ * HD_;

    // ---- issue Q loads (rows of 128B, swizzled) + KV tile 0
    {
        const int row = tid >> 1;
        const int u0 = (tid & 1) * 4;
        const long gq = bhoff + (long)(qt * 128 + row) * HD_;
        #pragma unroll
        for (int i = 0; i < 4; i++) {
            const int u = u0 + i;
            const uint32_t so = row * 128 + ((u ^ (row & 7)) << 4);
            CP_ASYNC16(sb + so,         g_qh + gq + u * 8);
            CP_ASYNC16(sb + 16384 + so, g_ql + gq + u * 8);
        }
    }
    const int kvp = tid >> 6;        // 0..3 -> Kh,Kl,Vh,Vl
    const int kvr = tid & 63;        // row within tile
    const __nv_bfloat16* kvsrc =
        (kvp == 0) ? g_kh : (kvp == 1) ? g_kl : (kvp == 2) ? g_vh : g_vl;
    const uint32_t kvdst_off = kvp * 8192 + kvr * 128;

    auto load_kv = [&](int kb, int buf) {
        const uint32_t st = sb + 32768 + buf * 32768;
        const long gs = bhoff + (long)(kb * 64 + kvr) * HD_;
        #pragma unroll
        for (int u = 0; u < 8; u++)
            CP_ASYNC16(st + kvdst_off + ((u ^ (kvr & 7)) << 4), kvsrc + gs + u * 8);
    };
    load_kv(0, 0);
    CP_COMMIT();
    CP_WAIT0();
    __syncthreads();

    // ---- Q fragments (A-frags, m16k16 per hd-step)
    uint32_t qh[4][4], ql[4][4];
    #pragma unroll
    for (int s = 0; s < 4; s++) {
        const int row = w * 16 + (lane & 15);
        const int ku = s * 2 + (lane >> 4);
        const uint32_t ad = sb + row * 128 + ((ku ^ (row & 7)) << 4);
        LDSM_X4(qh[s][0], qh[s][1], qh[s][2], qh[s][3], ad);
        LDSM_X4(ql[s][0], ql[s][1], ql[s][2], ql[s][3], ad + 16384);
    }

    float oacc[8][4] = {};
    float m2a = -1e30f, m2b = -1e30f;
    float la = 0.f, lb = 0.f;

    const int nt = 2 * qt + 2;
    for (int kb = 0; kb < nt; kb++) {
        if (kb > 0) CP_WAIT0();
        __syncthreads();
        if (kb + 1 < nt) { load_kv(kb + 1, (kb + 1) & 1); CP_COMMIT(); }

        if (kb * 64 > qbase + 15) continue;   // warp fully masked

        const uint32_t stK = sb + 32768 + (kb & 1) * 32768;
        const uint32_t stV = stK + 16384;

        // ---- S = Q K^T (bf16x3)
        float sacc[8][4] = {};
        #pragma unroll
        for (int s = 0; s < 4; s++) {
            #pragma unroll
            for (int g = 0; g < 4; g++) {
                const int row = g * 16 + (lane & 15);
                const uint32_t ka = stK + row * 128 +
                    (((s * 2 + (lane >> 4)) ^ (row & 7)) << 4);
                uint32_t h0, h1, h2, h3, l0, l1, l2, l3;
                LDSM_X4(h0, h1, h2, h3, ka);
                LDSM_X4(l0, l1, l2, l3, ka + 8192);
                MMA_BF16(sacc[2 * g],     qh[s], h0, h2);
                MMA_BF16(sacc[2 * g],     ql[s], h0, h2);
                MMA_BF16(sacc[2 * g],     qh[s], l0, l2);
                MMA_BF16(sacc[2 * g + 1], qh[s], h1, h3);
                MMA_BF16(sacc[2 * g + 1], ql[s], h1, h3);
                MMA_BF16(sacc[2 * g + 1], qh[s], l1, l3);
            }
        }

        // ---- scale to log2-domain + causal mask + row max
        const bool needmask = (kb * 64 + 63) > r0;
        float mra = -1e30f, mrb = -1e30f;
        #pragma unroll
        for (int j = 0; j < 8; j++) {
            const int c0 = kb * 64 + 8 * j + 2 * ti, c1 = c0 + 1;
            float z0 = sacc[j][0] * SCL2;
            float z1 = sacc[j][1] * SCL2;
            float z2 = sacc[j][2] * SCL2;
            float z3 = sacc[j][3] * SCL2;
            if (needmask) {
                if (c0 > r0) z0 = -1e30f;
                if (c1 > r0) z1 = -1e30f;
                if (c0 > r0 + 8) z2 = -1e30f;
                if (c1 > r0 + 8) z3 = -1e30f;
            }
            sacc[j][0] = z0; sacc[j][1] = z1; sacc[j][2] = z2; sacc[j][3] = z3;
            mra = fmaxf(mra, fmaxf(z0, z1));
            mrb = fmaxf(mrb, fmaxf(z2, z3));
        }
        mra = fmaxf(mra, __shfl_xor_sync(0xffffffffu, mra, 1));
        mra = fmaxf(mra, __shfl_xor_sync(0xffffffffu, mra, 2));
        mrb = fmaxf(mrb, __shfl_xor_sync(0xffffffffu, mrb, 1));
        mrb = fmaxf(mrb, __shfl_xor_sync(0xffffffffu, mrb, 2));

        const float mna = fmaxf(m2a, mra);
        const float mnb = fmaxf(m2b, mrb);
        const float alpa = ex2(m2a - mna);
        const float alpb = ex2(m2b - mnb);
        m2a = mna; m2b = mnb;

        #pragma unroll
        for (int j = 0; j < 8; j++) {
            oacc[j][0] *= alpa; oacc[j][1] *= alpa;
            oacc[j][2] *= alpb; oacc[j][3] *= alpb;
        }

        // ---- exp + pack P hi/lo (A-frag layout!)
        uint32_t pha[8], phb[8], pla[8], plb[8];
        float sa = 0.f, sbm = 0.f;
        #pragma unroll
        for (int j = 0; j < 8; j++) {
            float p0 = ex2(sacc[j][0] - m2a);
            float p1 = ex2(sacc[j][1] - m2a);
            float p2 = ex2(sacc[j][2] - m2b);
            float p3 = ex2(sacc[j][3] - m2b);
            sa += p0 + p1; sbm += p2 + p3;
            pha[j] = pack2bf(p0, p1); pla[j] = resid2bf(pha[j], p0, p1);
            phb[j] = pack2bf(p2, p3); plb[j] = resid2bf(phb[j], p2, p3);
        }
        sa  += __shfl_xor_sync(0xffffffffu, sa, 1);
        sa  += __shfl_xor_sync(0xffffffffu, sa, 2);
        sbm += __shfl_xor_sync(0xffffffffu, sbm, 1);
        sbm += __shfl_xor_sync(0xffffffffu, sbm, 2);
        la = la * alpa + sa;
        lb = lb * alpb + sbm;

        // ---- O += P V (bf16x3)
        #pragma unroll
        for (int s = 0; s < 4; s++) {
            uint32_t aH[4] = {pha[2 * s], phb[2 * s], pha[2 * s + 1], phb[2 * s + 1]};
            uint32_t aL[4] = {pla[2 * s], plb[2 * s], pla[2 * s + 1], plb[2 * s + 1]};
            #pragma unroll
            for (int b = 0; b < 4; b++) {
                const int krow = s * 16 + (lane & 15);
                const uint32_t va = stV + krow * 128 +
                    (((b * 2 + (lane >> 4)) ^ (krow & 7)) << 4);
                uint32_t h0, h1, h2, h3, l0, l1, l2, l3;
                LDSM_X4T(h0, h1, h2, h3, va);
                MMA_BF16(oacc[2 * b],     aH, h0, h1);
                MMA_BF16(oacc[2 * b],     aL, h0, h1);
                MMA_BF16(oacc[2 * b + 1], aH, h2, h3);
                MMA_BF16(oacc[2 * b + 1], aL, h2, h3);
                LDSM_X4T(l0, l1, l2, l3, va + 8192);
                MMA_BF16(oacc[2 * b],     aH, l0, l1);
                MMA_BF16(oacc[2 * b + 1], aH, l2, l3);
            }
        }
    }

    // ---- epilogue: normalize, bf16 hi/lo split, write [B,T,H*HD]
    const float inva = 1.0f / la, invb = 1.0f / lb;
    const int bidx = bh >> 4, h = bh & 15;
    const long rowa = ((long)(bidx * T_ + qbase + tg)) * D_ + h * HD_;
    const long rowb = rowa + 8L * D_;
    #pragma unroll
    for (int j = 0; j < 8; j++) {
        const int col = 8 * j + 2 * ti;
        float f0 = oacc[j][0] * inva, f1 = oacc[j][1] * inva;
        float f2 = oacc[j][2] * invb, f3 = oacc[j][3] * invb;
        uint32_t hpa = pack2bf(f0, f1);
        uint32_t hpb = pack2bf(f2, f3);
        *(uint32_t*)(g_ahi + rowa + col) = hpa;
        *(uint32_t*)(g_alo + rowa + col) = resid2bf(hpa, f0, f1);
        *(uint32_t*)(g_ahi + rowb + col) = hpb;
        *(uint32_t*)(g_alo + rowb + col) = resid2bf(hpb, f2, f3);
    }
}

// ---------------------------------------------------------------------------
extern "C" void kernel_launch(void* const* d_in, const int* in_sizes, int n_in,
                              void* d_out, int out_size)
{
    const float* x      = (const float*)d_in[0];
    const float* w_qkv  = (const float*)d_in[1];
    const float* b_qkv  = (const float*)d_in[2];
    const float* w_proj = (const float*)d_in[3];
    const float* b_proj = (const float*)d_in[4];
    float* out = (float*)d_out;

    __nv_bfloat16 *xhi, *xlo, *wqhi, *wqlo, *wphi, *wplo, *ahi, *alo;
    cudaGetSymbolAddress((void**)&xhi,  g_xhi);
    cudaGetSymbolAddress((void**)&xlo,  g_xlo);
    cudaGetSymbolAddress((void**)&wqhi, g_wqhi);
    cudaGetSymbolAddress((void**)&wqlo, g_wqlo);
    cudaGetSymbolAddress((void**)&wphi, g_wphi);
    cudaGetSymbolAddress((void**)&wplo, g_wplo);
    cudaGetSymbolAddress((void**)&ahi,  g_ahi);
    cudaGetSymbolAddress((void**)&alo,  g_alo);

    // 0) bf16 hi/lo splits
    split_kernel<<<(M_ * D_) / 1024, 256>>>(x, xhi, xlo, M_ * D_);
    split_kernel<<<(D_ * 3 * D_) / 1024, 256>>>(w_qkv, wqhi, wqlo, D_ * 3 * D_);
    split_kernel<<<(D_ * D_) / 1024, 256>>>(w_proj, wphi, wplo, D_ * D_);

    // 1) QKV GEMM (bf16x3) -> q/k/v bf16 hi/lo
    cudaFuncSetAttribute((const void*)gemm_bf16x3<1>,
                         cudaFuncAttributeMaxDynamicSharedMemorySize, GEMM_SMEM);
    gemm_bf16x3<1><<<dim3(3 * D_ / 128, M_ / 128), 256, GEMM_SMEM>>>(
        xhi, xlo, wqhi, wqlo, b_qkv, nullptr, 3 * D_);

    // 2) tensor-core flash attention
    cudaFuncSetAttribute((const void*)attn_tc_kernel,
                         cudaFuncAttributeMaxDynamicSharedMemorySize, ATTN_SMEM);
    attn_tc_kernel<<<dim3(T_ / 128, B_ * H_), 256, ATTN_SMEM>>>();

    // 3) proj GEMM (bf16x3)
    cudaFuncSetAttribute((const void*)gemm_bf16x3<0>,
                         cudaFuncAttributeMaxDynamicSharedMemorySize, GEMM_SMEM);
    gemm_bf16x3<0><<<dim3(D_ / 128, M_ / 128), 256, GEMM_SMEM>>>(
        ahi, alo, wphi, wplo, b_proj, out, D_);
}

// round 6
// speedup vs baseline: 2.9554x; 1.0124x over previous
#include <cuda_runtime.h>
#include <cuda_bf16.h>
#include <cstdint>

// Problem constants
#define B_  4
#define T_  2048
#define D_  1024
#define H_  16
#define HD_ 64
#define M_  (B_ * T_)        // 8192

// Scratch (device globals — no allocation allowed)
__device__ __nv_bfloat16 g_qh[B_ * H_ * T_ * HD_];   // [B,H,T,HD] hi/lo
__device__ __nv_bfloat16 g_ql[B_ * H_ * T_ * HD_];
__device__ __nv_bfloat16 g_kh[B_ * H_ * T_ * HD_];
__device__ __nv_bfloat16 g_kl[B_ * H_ * T_ * HD_];
__device__ __nv_bfloat16 g_vh[B_ * H_ * T_ * HD_];
__device__ __nv_bfloat16 g_vl[B_ * H_ * T_ * HD_];
__device__ __nv_bfloat16 g_xhi[M_ * D_];        // x split       [M,K]
__device__ __nv_bfloat16 g_xlo[M_ * D_];
__device__ __nv_bfloat16 g_wqhi[D_ * 3 * D_];   // w_qkv split   [K,N]
__device__ __nv_bfloat16 g_wqlo[D_ * 3 * D_];
__device__ __nv_bfloat16 g_wphi[D_ * D_];       // w_proj split  [K,N]
__device__ __nv_bfloat16 g_wplo[D_ * D_];
__device__ __nv_bfloat16 g_ahi[M_ * D_];        // attention out [M,K]
__device__ __nv_bfloat16 g_alo[M_ * D_];

// ---------------------------------------------------------------------------
__device__ __forceinline__ uint32_t smem_u32(const void* p) {
    uint32_t a;
    asm("{ .reg .u64 t; cvta.to.shared.u64 t, %1; cvt.u32.u64 %0, t; }"
        : "=r"(a) : "l"(p));
    return a;
}

#define CP_ASYNC16(saddr, gaddr) \
    asm volatile("cp.async.cg.shared.global [%0], [%1], 16;" \
                 :: "r"(saddr), "l"(gaddr))
#define CP_COMMIT()  asm volatile("cp.async.commit_group;")
#define CP_WAIT1()   asm volatile("cp.async.wait_group 1;")
#define CP_WAIT0()   asm volatile("cp.async.wait_group 0;")

#define LDSM_X4(r0, r1, r2, r3, addr) \
    asm volatile("ldmatrix.sync.aligned.m8n8.x4.shared.b16 {%0,%1,%2,%3}, [%4];" \
                 : "=r"(r0), "=r"(r1), "=r"(r2), "=r"(r3) : "r"(addr))
#define LDSM_X4T(r0, r1, r2, r3, addr) \
    asm volatile("ldmatrix.sync.aligned.m8n8.x4.trans.shared.b16 {%0,%1,%2,%3}, [%4];" \
                 : "=r"(r0), "=r"(r1), "=r"(r2), "=r"(r3) : "r"(addr))

#define MMA_BF16(c, a, b0, b1) \
    asm volatile("mma.sync.aligned.m16n8k16.row.col.f32.bf16.bf16.f32 " \
        "{%0,%1,%2,%3}, {%4,%5,%6,%7}, {%8,%9}, {%0,%1,%2,%3};" \
        : "+f"((c)[0]), "+f"((c)[1]), "+f"((c)[2]), "+f"((c)[3]) \
        : "r"((a)[0]), "r"((a)[1]), "r"((a)[2]), "r"((a)[3]), "r"(b0), "r"(b1))

// pack two fp32 -> bf16x2 (lo in low half)
__device__ __forceinline__ uint32_t pack2bf(float lo, float hi) {
    uint32_t r;
    asm("cvt.rn.bf16x2.f32 %0, %1, %2;" : "=r"(r) : "f"(hi), "f"(lo));
    return r;
}
// residual pack: (lo,hi) - bf16(lo,hi)
__device__ __forceinline__ uint32_t resid2bf(uint32_t h, float lo, float hi) {
    float lf = __uint_as_float(h << 16);
    float hf = __uint_as_float(h & 0xffff0000u);
    return pack2bf(lo - lf, hi - hf);
}
__device__ __forceinline__ float ex2(float x) {
    float r;
    asm("ex2.approx.f32 %0, %1;" : "=f"(r) : "f"(x));
    return r;
}

// ---------------------------------------------------------------------------
// Prep: elementwise fp32 -> bf16 hi/lo split
// ---------------------------------------------------------------------------
__global__ void split_kernel(const float* __restrict__ src,
                             __nv_bfloat16* __restrict__ hi,
                             __nv_bfloat16* __restrict__ lo, int n)
{
    int i = (blockIdx.x * 256 + threadIdx.x) * 4;
    if (i >= n) return;
    float4 v = *(const float4*)(src + i);
    uint32_t h0 = pack2bf(v.x, v.y), h1 = pack2bf(v.z, v.w);
    uint32_t l0 = resid2bf(h0, v.x, v.y), l1 = resid2bf(h1, v.z, v.w);
    *(uint2*)(hi + i) = make_uint2(h0, h1);
    *(uint2*)(lo + i) = make_uint2(l0, l1);
}

// ---------------------------------------------------------------------------
// bf16x3 GEMM via mma.sync.  3-stage cp.async pipeline, ONE __syncthreads per
// k-chunk: at iter c, wait_group(1) completes stage c (c+1 in flight); the
// barrier also proves stage c-1 was consumed, so loading stage c+2 into
// buffer (c+2)%3 == (c-1)%3 is race-free.
// EPI=0: plain store.  EPI=1: QKV scatter into bf16 hi/lo q/k/v.
// ---------------------------------------------------------------------------
#define GEMM_SMEM (3 * 32768)

template <int EPI>
__global__ __launch_bounds__(256, 2) void gemm_bf16x3(
    const __nv_bfloat16* __restrict__ Ahi, const __nv_bfloat16* __restrict__ Alo,
    const __nv_bfloat16* __restrict__ Bhi, const __nv_bfloat16* __restrict__ Blo,
    const float* __restrict__ bias, float* __restrict__ C, int N)
{
    extern __shared__ char sm[];
    const uint32_t sb = smem_u32(sm);
    const int tid = threadIdx.x;
    const int warp = tid >> 5, lane = tid & 31;
    const int m0 = blockIdx.y * 128, n0 = blockIdx.x * 128;
    const int K = 1024;

    const int a_r0 = (tid * 2) >> 2,     a_c0 = (tid * 2) & 3;
    const int a_r1 = (tid * 2 + 1) >> 2, a_c1 = (tid * 2 + 1) & 3;
    const int b_r0 = (tid * 2) >> 4,     b_c0 = (tid * 2) & 15;
    const int b_r1 = (tid * 2 + 1) >> 4, b_c1 = (tid * 2 + 1) & 15;

    auto load_stage = [&](int c, int buf) {
        const uint32_t st = sb + buf * 32768;
        #pragma unroll
        for (int part = 0; part < 2; part++) {
            const __nv_bfloat16* Ap = part ? Alo : Ahi;
            const __nv_bfloat16* Bp = part ? Blo : Bhi;
            const uint32_t ao = st + part * 8192;
            const uint32_t bo = st + 16384 + part * 8192;
            CP_ASYNC16(ao + a_r0 * 64 + ((a_c0 ^ (a_r0 & 3)) << 4),
                       Ap + (long)(m0 + a_r0) * K + c * 32 + a_c0 * 8);
            CP_ASYNC16(ao + a_r1 * 64 + ((a_c1 ^ (a_r1 & 3)) << 4),
                       Ap + (long)(m0 + a_r1) * K + c * 32 + a_c1 * 8);
            CP_ASYNC16(bo + b_r0 * 256 + ((b_c0 ^ (b_r0 & 7)) << 4),
                       Bp + (long)(c * 32 + b_r0) * N + n0 + b_c0 * 8);
            CP_ASYNC16(bo + b_r1 * 256 + ((b_c1 ^ (b_r1 & 7)) << 4),
                       Bp + (long)(c * 32 + b_r1) * N + n0 + b_c1 * 8);
        }
        CP_COMMIT();
    };

    const int wm = (warp & 1) * 64;
    const int wn = (warp >> 1) * 32;

    float acc[4][4][4] = {};

    const int a_lr = lane & 15;
    const int a_lk = lane >> 4;
    const int b_lk = lane & 15;
    const int b_ln = lane >> 4;
    const int nu0 = wn >> 3;

    load_stage(0, 0);
    load_stage(1, 1);

    int buf = 0;                 // c % 3
    for (int c = 0; c < 32; c++) {
        if (c < 31) CP_WAIT1(); else CP_WAIT0();
        __syncthreads();
        if (c + 2 < 32) {
            int nb = buf + 2; if (nb >= 3) nb -= 3;
            load_stage(c + 2, nb);
        }

        const uint32_t st = sb + buf * 32768;
        #pragma unroll
        for (int ks = 0; ks < 2; ks++) {
            uint32_t ah[4][4], al[4][4];
            #pragma unroll
            for (int mi = 0; mi < 4; mi++) {
                const int row = wm + mi * 16 + a_lr;
                const int ku = ks * 2 + a_lk;
                const uint32_t off = row * 64 + ((ku ^ (row & 3)) << 4);
                LDSM_X4(ah[mi][0], ah[mi][1], ah[mi][2], ah[mi][3], st + off);
                LDSM_X4(al[mi][0], al[mi][1], al[mi][2], al[mi][3], st + 8192 + off);
            }
            #pragma unroll
            for (int bi = 0; bi < 2; bi++) {
                const int krow = ks * 16 + b_lk;
                const int nu = nu0 + bi * 2 + b_ln;
                const uint32_t boff = krow * 256 + ((nu ^ (krow & 7)) << 4);
                uint32_t bh[4], bl[4];
                LDSM_X4T(bh[0], bh[1], bh[2], bh[3], st + 16384 + boff);
                LDSM_X4T(bl[0], bl[1], bl[2], bl[3], st + 24576 + boff);
                #pragma unroll
                for (int mi = 0; mi < 4; mi++) {
                    MMA_BF16(acc[mi][bi * 2],     ah[mi], bh[0], bh[1]);
                    MMA_BF16(acc[mi][bi * 2],     ah[mi], bl[0], bl[1]);
                    MMA_BF16(acc[mi][bi * 2],     al[mi], bh[0], bh[1]);
                    MMA_BF16(acc[mi][bi * 2 + 1], ah[mi], bh[2], bh[3]);
                    MMA_BF16(acc[mi][bi * 2 + 1], ah[mi], bl[2], bl[3]);
                    MMA_BF16(acc[mi][bi * 2 + 1], al[mi], bh[2], bh[3]);
                }
            }
        }
        if (++buf == 3) buf = 0;
    }

    // Epilogue
    const int tg = lane >> 2, ti = lane & 3;
    #pragma unroll
    for (int mi = 0; mi < 4; mi++) {
        #pragma unroll
        for (int nj = 0; nj < 4; nj++) {
            const int n = n0 + wn + nj * 8 + ti * 2;
            const float bx = __ldg(&bias[n]), by = __ldg(&bias[n + 1]);
            #pragma unroll
            for (int half = 0; half < 2; half++) {
                const int m = m0 + wm + mi * 16 + tg + half * 8;
                float ox = acc[mi][nj][half * 2 + 0] + bx;
                float oy = acc[mi][nj][half * 2 + 1] + by;
                if (EPI == 0) {
                    *(float2*)(C + (long)m * N + n) = make_float2(ox, oy);
                } else {
                    const int bidx = m >> 11, t = m & (T_ - 1);
                    const int which = n >> 10;
                    const int rem = n & 1023;
                    const int h = rem >> 6, hd = rem & 63;
                    __nv_bfloat16* dh = (which == 0) ? g_qh : ((which == 1) ? g_kh : g_vh);
                    __nv_bfloat16* dl = (which == 0) ? g_ql : ((which == 1) ? g_kl : g_vl);
                    long off = (((long)bidx * H_ + h) * T_ + t) * HD_ + hd;
                    uint32_t hp = pack2bf(ox, oy);
                    *(uint32_t*)(dh + off) = hp;
                    *(uint32_t*)(dl + off) = resid2bf(hp, ox, oy);
                }
            }
        }
    }
}

// ---------------------------------------------------------------------------
// Tensor-core causal flash attention (bf16x3), FA2 register softmax.
// CTA: 128 q-rows, 8 warps x m16.  kv tiles of 64, cp.async double buffer.
// smem: Qh/Ql 32KB + 2 stages x (Kh,Kl,Vh,Vl 8KB each) = 96KB.
// ---------------------------------------------------------------------------
#define ATTN_SMEM (32768 + 2 * 32768)
#define SCL2 0.1803368801111204f   // 0.125 * log2(e)

__global__ __launch_bounds__(256, 1) void attn_tc_kernel()
{
    extern __shared__ char sm[];
    const uint32_t sb = smem_u32(sm);
    const int tid = threadIdx.x;
    const int w = tid >> 5, lane = tid & 31;
    const int tg = lane >> 2, ti = lane & 3;
    const int qt = 15 - blockIdx.x;           // big tiles first
    const int bh = blockIdx.y;
    const int qbase = qt * 128 + w * 16;
    const int r0 = qbase + tg;                // thread rows r0, r0+8

    const long bhoff = (long)bh * T_ * HD_;

    // ---- issue Q loads (rows of 128B, swizzled) + KV tile 0
    {
        const int row = tid >> 1;
        const int u0 = (tid & 1) * 4;
        const long gq = bhoff + (long)(qt * 128 + row) * HD_;
        #pragma unroll
        for (int i = 0; i < 4; i++) {
            const int u = u0 + i;
            const uint32_t so = row * 128 + ((u ^ (row & 7)) << 4);
            CP_ASYNC16(sb + so,         g_qh + gq + u * 8);
            CP_ASYNC16(sb + 16384 + so, g_ql + gq + u * 8);
        }
    }
    const int kvp = tid >> 6;        // 0..3 -> Kh,Kl,Vh,Vl
    const int kvr = tid & 63;        // row within tile
    const __nv_bfloat16* kvsrc =
        (kvp == 0) ? g_kh : (kvp == 1) ? g_kl : (kvp == 2) ? g_vh : g_vl;
    const uint32_t kvdst_off = kvp * 8192 + kvr * 128;

    auto load_kv = [&](int kb, int buf) {
        const uint32_t st = sb + 32768 + buf * 32768;
        const long gs = bhoff + (long)(kb * 64 + kvr) * HD_;
        #pragma unroll
        for (int u = 0; u < 8; u++)
            CP_ASYNC16(st + kvdst_off + ((u ^ (kvr & 7)) << 4), kvsrc + gs + u * 8);
    };
    load_kv(0, 0);
    CP_COMMIT();
    CP_WAIT0();
    __syncthreads();

    // ---- Q fragments (A-frags, m16k16 per hd-step)
    uint32_t qh[4][4], ql[4][4];
    #pragma unroll
    for (int s = 0; s < 4; s++) {
        const int row = w * 16 + (lane & 15);
        const int ku = s * 2 + (lane >> 4);
        const uint32_t ad = sb + row * 128 + ((ku ^ (row & 7)) << 4);
        LDSM_X4(qh[s][0], qh[s][1], qh[s][2], qh[s][3], ad);
        LDSM_X4(ql[s][0], ql[s][1], ql[s][2], ql[s][3], ad + 16384);
    }

    float oacc[8][4] = {};
    float m2a = -1e30f, m2b = -1e30f;
    float la = 0.f, lb = 0.f;

    const int nt = 2 * qt + 2;
    for (int kb = 0; kb < nt; kb++) {
        if (kb > 0) CP_WAIT0();
        __syncthreads();
        if (kb + 1 < nt) { load_kv(kb + 1, (kb + 1) & 1); CP_COMMIT(); }

        if (kb * 64 > qbase + 15) continue;   // warp fully masked

        const uint32_t stK = sb + 32768 + (kb & 1) * 32768;
        const uint32_t stV = stK + 16384;

        // ---- S = Q K^T (bf16x3)
        float sacc[8][4] = {};
        #pragma unroll
        for (int s = 0; s < 4; s++) {
            #pragma unroll
            for (int g = 0; g < 4; g++) {
                const int row = g * 16 + (lane & 15);
                const uint32_t ka = stK + row * 128 +
                    (((s * 2 + (lane >> 4)) ^ (row & 7)) << 4);
                uint32_t h0, h1, h2, h3, l0, l1, l2, l3;
                LDSM_X4(h0, h1, h2, h3, ka);
                LDSM_X4(l0, l1, l2, l3, ka + 8192);
                MMA_BF16(sacc[2 * g],     qh[s], h0, h2);
                MMA_BF16(sacc[2 * g],     ql[s], h0, h2);
                MMA_BF16(sacc[2 * g],     qh[s], l0, l2);
                MMA_BF16(sacc[2 * g + 1], qh[s], h1, h3);
                MMA_BF16(sacc[2 * g + 1], ql[s], h1, h3);
                MMA_BF16(sacc[2 * g + 1], qh[s], l1, l3);
            }
        }

        // ---- scale to log2-domain + causal mask + row max
        const bool needmask = (kb * 64 + 63) > r0;
        float mra = -1e30f, mrb = -1e30f;
        #pragma unroll
        for (int j = 0; j < 8; j++) {
            const int c0 = kb * 64 + 8 * j + 2 * ti, c1 = c0 + 1;
            float z0 = sacc[j][0] * SCL2;
            float z1 = sacc[j][1] * SCL2;
            float z2 = sacc[j][2] * SCL2;
            float z3 = sacc[j][3] * SCL2;
            if (needmask) {
                if (c0 > r0) z0 = -1e30f;
                if (c1 > r0) z1 = -1e30f;
                if (c0 > r0 + 8) z2 = -1e30f;
                if (c1 > r0 + 8) z3 = -1e30f;
            }
            sacc[j][0] = z0; sacc[j][1] = z1; sacc[j][2] = z2; sacc[j][3] = z3;
            mra = fmaxf(mra, fmaxf(z0, z1));
            mrb = fmaxf(mrb, fmaxf(z2, z3));
        }
        mra = fmaxf(mra, __shfl_xor_sync(0xffffffffu, mra, 1));
        mra = fmaxf(mra, __shfl_xor_sync(0xffffffffu, mra, 2));
        mrb = fmaxf(mrb, __shfl_xor_sync(0xffffffffu, mrb, 1));
        mrb = fmaxf(mrb, __shfl_xor_sync(0xffffffffu, mrb, 2));

        const float mna = fmaxf(m2a, mra);
        const float mnb = fmaxf(m2b, mrb);
        const float alpa = ex2(m2a - mna);
        const float alpb = ex2(m2b - mnb);
        m2a = mna; m2b = mnb;

        #pragma unroll
        for (int j = 0; j < 8; j++) {
            oacc[j][0] *= alpa; oacc[j][1] *= alpa;
            oacc[j][2] *= alpb; oacc[j][3] *= alpb;
        }

        // ---- exp + pack P hi/lo (A-frag layout!)
        uint32_t pha[8], phb[8], pla[8], plb[8];
        float sa = 0.f, sbm = 0.f;
        #pragma unroll
        for (int j = 0; j < 8; j++) {
            float p0 = ex2(sacc[j][0] - m2a);
            float p1 = ex2(sacc[j][1] - m2a);
            float p2 = ex2(sacc[j][2] - m2b);
            float p3 = ex2(sacc[j][3] - m2b);
            sa += p0 + p1; sbm += p2 + p3;
            pha[j] = pack2bf(p0, p1); pla[j] = resid2bf(pha[j], p0, p1);
            phb[j] = pack2bf(p2, p3); plb[j] = resid2bf(phb[j], p2, p3);
        }
        sa  += __shfl_xor_sync(0xffffffffu, sa, 1);
        sa  += __shfl_xor_sync(0xffffffffu, sa, 2);
        sbm += __shfl_xor_sync(0xffffffffu, sbm, 1);
        sbm += __shfl_xor_sync(0xffffffffu, sbm, 2);
        la = la * alpa + sa;
        lb = lb * alpb + sbm;

        // ---- O += P V (bf16x3)
        #pragma unroll
        for (int s = 0; s < 4; s++) {
            uint32_t aH[4] = {pha[2 * s], phb[2 * s], pha[2 * s + 1], phb[2 * s + 1]};
            uint32_t aL[4] = {pla[2 * s], plb[2 * s], pla[2 * s + 1], plb[2 * s + 1]};
            #pragma unroll
            for (int b = 0; b < 4; b++) {
                const int krow = s * 16 + (lane & 15);
                const uint32_t va = stV + krow * 128 +
                    (((b * 2 + (lane >> 4)) ^ (krow & 7)) << 4);
                uint32_t h0, h1, h2, h3, l0, l1, l2, l3;
                LDSM_X4T(h0, h1, h2, h3, va);
                MMA_BF16(oacc[2 * b],     aH, h0, h1);
                MMA_BF16(oacc[2 * b],     aL, h0, h1);
                MMA_BF16(oacc[2 * b + 1], aH, h2, h3);
                MMA_BF16(oacc[2 * b + 1], aL, h2, h3);
                LDSM_X4T(l0, l1, l2, l3, va + 8192);
                MMA_BF16(oacc[2 * b],     aH, l0, l1);
                MMA_BF16(oacc[2 * b + 1], aH, l2, l3);
            }
        }
    }

    // ---- epilogue: normalize, bf16 hi/lo split, write [B,T,H*HD]
    const float inva = 1.0f / la, invb = 1.0f / lb;
    const int bidx = bh >> 4, h = bh & 15;
    const long rowa = ((long)(bidx * T_ + qbase + tg)) * D_ + h * HD_;
    const long rowb = rowa + 8L * D_;
    #pragma unroll
    for (int j = 0; j < 8; j++) {
        const int col = 8 * j + 2 * ti;
        float f0 = oacc[j][0] * inva, f1 = oacc[j][1] * inva;
        float f2 = oacc[j][2] * invb, f3 = oacc[j][3] * invb;
        uint32_t hpa = pack2bf(f0, f1);
        uint32_t hpb = pack2bf(f2, f3);
        *(uint32_t*)(g_ahi + rowa + col) = hpa;
        *(uint32_t*)(g_alo + rowa + col) = resid2bf(hpa, f0, f1);
        *(uint32_t*)(g_ahi + rowb + col) = hpb;
        *(uint32_t*)(g_alo + rowb + col) = resid2bf(hpb, f2, f3);
    }
}

// ---------------------------------------------------------------------------
extern "C" void kernel_launch(void* const* d_in, const int* in_sizes, int n_in,
                              void* d_out, int out_size)
{
    const float* x      = (const float*)d_in[0];
    const float* w_qkv  = (const float*)d_in[1];
    const float* b_qkv  = (const float*)d_in[2];
    const float* w_proj = (const float*)d_in[3];
    const float* b_proj = (const float*)d_in[4];
    float* out = (float*)d_out;

    __nv_bfloat16 *xhi, *xlo, *wqhi, *wqlo, *wphi, *wplo, *ahi, *alo;
    cudaGetSymbolAddress((void**)&xhi,  g_xhi);
    cudaGetSymbolAddress((void**)&xlo,  g_xlo);
    cudaGetSymbolAddress((void**)&wqhi, g_wqhi);
    cudaGetSymbolAddress((void**)&wqlo, g_wqlo);
    cudaGetSymbolAddress((void**)&wphi, g_wphi);
    cudaGetSymbolAddress((void**)&wplo, g_wplo);
    cudaGetSymbolAddress((void**)&ahi,  g_ahi);
    cudaGetSymbolAddress((void**)&alo,  g_alo);

    // 0) bf16 hi/lo splits
    split_kernel<<<(M_ * D_) / 1024, 256>>>(x, xhi, xlo, M_ * D_);
    split_kernel<<<(D_ * 3 * D_) / 1024, 256>>>(w_qkv, wqhi, wqlo, D_ * 3 * D_);
    split_kernel<<<(D_ * D_) / 1024, 256>>>(w_proj, wphi, wplo, D_ * D_);

    // 1) QKV GEMM (bf16x3) -> q/k/v bf16 hi/lo
    cudaFuncSetAttribute((const void*)gemm_bf16x3<1>,
                         cudaFuncAttributeMaxDynamicSharedMemorySize, GEMM_SMEM);
    gemm_bf16x3<1><<<dim3(3 * D_ / 128, M_ / 128), 256, GEMM_SMEM>>>(
        xhi, xlo, wqhi, wqlo, b_qkv, nullptr, 3 * D_);

    // 2) tensor-core flash attention
    cudaFuncSetAttribute((const void*)attn_tc_kernel,
                         cudaFuncAttributeMaxDynamicSharedMemorySize, ATTN_SMEM);
    attn_tc_kernel<<<dim3(T_ / 128, B_ * H_), 256, ATTN_SMEM>>>();

    // 3) proj GEMM (bf16x3)
    cudaFuncSetAttribute((const void*)gemm_bf16x3<0>,
                         cudaFuncAttributeMaxDynamicSharedMemorySize, GEMM_SMEM);
    gemm_bf16x3<0><<<dim3(D_ / 128, M_ / 128), 256, GEMM_SMEM>>>(
        ahi, alo, wphi, wplo, b_proj, out, D_);
}